// round 11
// baseline (speedup 1.0000x reference)
#include <cuda_runtime.h>
#include <math.h>
#include <stdint.h>
#include <mma.h>

using namespace nvcuda;

#define QLEN 512
#define MLEN 512
#define KLEN 1024          // QLEN + MLEN
#define BSZ 8
#define NH 16
#define DH 64
#define DM 1024
#define HD 1024            // NH*DH
#define DI 4096
#define NLAYER 6
#define VOCAB 32000
#define ATT_SCALE 0.125f   // 1/sqrt(64)
#define NEGV -1e30f

#define NROW (QLEN*BSZ)        // 4096
#define KROW (KLEN*BSZ)        // 8192

// ---------------- scratch (static device globals; no runtime allocation) ---------
#define SCORE_ELEMS ((size_t)BSZ*NH*QLEN*KLEN)            // 67,108,864 floats
#define LOGIT_ELEMS ((size_t)NROW*VOCAB)                  // 131,072,000 floats
#define BIG_ELEMS   (2*SCORE_ELEMS)
static_assert(BIG_ELEMS >= LOGIT_ELEMS, "g_big must also fit logits");
__device__ float g_big   [BIG_ELEMS];
__device__ float g_core  [(size_t)NROW*DM];
__device__ float g_xmem  [(size_t)KROW*DM];
__device__ float g_pos   [(size_t)KLEN*DM];
__device__ float g_q     [(size_t)NROW*HD];
__device__ float g_kv    [(size_t)KROW*2*HD];
__device__ float g_rk    [(size_t)KLEN*HD];
__device__ float g_vec   [(size_t)NROW*HD];
__device__ float g_ff    [(size_t)NROW*DI];
__device__ float g_tmp   [(size_t)NROW*DM];

__device__ __forceinline__ float to_tf32(float x) {
    float y;
    asm("cvt.rna.tf32.f32 %0, %1;" : "=f"(y) : "f"(x));
    return y;
}

__device__ __forceinline__ uint32_t smem_u32(const void* p) {
    uint32_t a;
    asm("{ .reg .u64 t; cvta.to.shared.u64 t, %1; cvt.u32.u64 %0, t; }"
        : "=r"(a) : "l"(p));
    return a;
}

__device__ __forceinline__ void cp_async16(uint32_t saddr, const void* gptr) {
    asm volatile("cp.async.ca.shared.global [%0], [%1], 16;"
        :: "r"(saddr), "l"(gptr) : "memory");
}
#define CP_COMMIT()  asm volatile("cp.async.commit_group;" ::: "memory")
#define CP_WAIT(n)   asm volatile("cp.async.wait_group %0;" :: "n"(n) : "memory")

typedef wmma::fragment<wmma::matrix_a, 16, 16, 8, wmma::precision::tf32, wmma::row_major> FragAR;
typedef wmma::fragment<wmma::matrix_b, 16, 16, 8, wmma::precision::tf32, wmma::row_major> FragBR;
typedef wmma::fragment<wmma::matrix_b, 16, 16, 8, wmma::precision::tf32, wmma::col_major> FragBC;
typedef wmma::fragment<wmma::matrix_a, 16, 16, 8, wmma::precision::tf32, wmma::col_major> FragA;
typedef wmma::fragment<wmma::matrix_b, 16, 16, 8, wmma::precision::tf32, wmma::row_major> FragB;
typedef wmma::fragment<wmma::accumulator, 16, 16, 8, float> FragC;

// ---------------- small utility kernels ----------------

__global__ void k_copy4(const float4* __restrict__ src, float4* __restrict__ dst, int n4) {
    int i = blockIdx.x * blockDim.x + threadIdx.x;
    if (i < n4) dst[i] = src[i];
}

__global__ void k_embed(const int* __restrict__ data, const float* __restrict__ embW,
                        float* __restrict__ core) {
    int r = blockIdx.x;
    int tok = data[r];
    const float4* s = (const float4*)(embW + (size_t)tok * DM);
    float4* d = (float4*)(core + (size_t)r * DM);
    d[threadIdx.x] = s[threadIdx.x];
}

__global__ void k_pos(float* __restrict__ pos) {
    int p = blockIdx.x;
    int d = blockIdx.y * 256 + threadIdx.x;
    float ps = (float)(KLEN - 1 - p);
    int idx = (d < DM/2) ? d : (d - DM/2);
    float e = (float)(2 * idx) / (float)DM;
    float inv = powf(10000.0f, -e);
    float v = ps * inv;
    pos[(size_t)p * DM + d] = (d < DM/2) ? sinf(v) : cosf(v);
}

// ---------------- tf32 WMMA GEMM, 128x256 tile, 3-stage cp.async pipeline --------
// C[M,N] = A[M,K] @ B (+bias)(+relu).  BNK==0: B is [K][N];  BNK==1: B is [N][K].
// A tile in smem: [128][20] row-major (fp32 raw).  B tile: mode0 [16][264], mode1 [256][20].
// tf32 rounding (cvt.rna) applied to fragment registers after smem load.
#define LDKA 20
#define LDNB 264
#define A_ST_FLTS (128 * LDKA)          // 2560 floats per stage
#define B_ST_FLTS 5120                  // max(16*264=4224, 256*20=5120)
#define BIAS_FLTS (16 * LDNB)
#define WG_SMEM ((3 * A_ST_FLTS + 3 * B_ST_FLTS + BIAS_FLTS) * 4)   // 109,056 B

template<int BNK>
__global__ void __launch_bounds__(256, 1)
k_wgemm(const float* __restrict__ A, const float* __restrict__ B,
        const float* __restrict__ bias, float* __restrict__ C,
        int M, int N, int K, int relu) {
    extern __shared__ float dsm[];
    float* As_f   = dsm;
    float* Bs_f   = dsm + 3 * A_ST_FLTS;
    float* bias_f = dsm + 3 * A_ST_FLTS + 3 * B_ST_FLTS;
    uint32_t As_u = smem_u32(As_f);
    uint32_t Bs_u = smem_u32(Bs_f);

    int tid = threadIdx.x;
    int bx = blockIdx.x, by = blockIdx.y;
    int warp = tid >> 5;
    int m_off = (warp >> 2) * 64;       // 0 or 64
    int n_off = (warp & 3) * 64;        // 0,64,128,192

    const float* Abase = A + (size_t)by * 128 * K;

    auto issue = [&](int it) {
        int s = it % 3;
        int k0 = it << 4;
        uint32_t aS = As_u + (uint32_t)(s * A_ST_FLTS) * 4;
        uint32_t bS = Bs_u + (uint32_t)(s * B_ST_FLTS) * 4;
        // A: 128 rows x 4 chunks = 512 chunks; 2 per thread
#pragma unroll
        for (int i = 0; i < 2; i++) {
            int idx = tid + i * 256;
            int row = idx >> 2, ch = idx & 3;
            cp_async16(aS + (uint32_t)(row * LDKA + ch * 4) * 4,
                       Abase + (size_t)row * K + k0 + ch * 4);
        }
        if (BNK == 0) {
            // B: 16 rows x 64 chunks = 1024; 4 per thread
#pragma unroll
            for (int i = 0; i < 4; i++) {
                int idx = tid + i * 256;
                int row = idx >> 6, ch = idx & 63;
                cp_async16(bS + (uint32_t)(row * LDNB + ch * 4) * 4,
                           B + (size_t)(k0 + row) * N + (size_t)bx * 256 + ch * 4);
            }
        } else {
            // B: 256 rows x 4 chunks = 1024; 4 per thread
#pragma unroll
            for (int i = 0; i < 4; i++) {
                int idx = tid + i * 256;
                int row = idx >> 2, ch = idx & 3;
                cp_async16(bS + (uint32_t)(row * LDKA + ch * 4) * 4,
                           B + (size_t)(bx * 256 + row) * K + k0 + ch * 4);
            }
        }
        CP_COMMIT();
    };

    if (bias) {
        for (int idx = tid; idx < 16 * 256; idx += 256) {
            int r = idx >> 8, n = idx & 255;
            bias_f[r * LDNB + n] = bias[(size_t)bx * 256 + n];
        }
    }

    int nIter = K >> 4;
    issue(0);
    issue(1);

    FragC c[4][4];
    __syncthreads();   // bias_s visible
#pragma unroll
    for (int i = 0; i < 4; i++)
#pragma unroll
        for (int j = 0; j < 4; j++) {
            if (bias) wmma::load_matrix_sync(c[i][j], bias_f + n_off + j * 16, LDNB,
                                             wmma::mem_row_major);
            else      wmma::fill_fragment(c[i][j], 0.0f);
        }

    for (int it = 0; it < nIter; it++) {
        int s = it % 3;
        if (it + 1 < nIter) { CP_WAIT(1); } else { CP_WAIT(0); }
        __syncthreads();
        if (it + 2 < nIter) issue(it + 2);

        const float* aT = As_f + s * A_ST_FLTS;
        const float* bT = Bs_f + s * B_ST_FLTS;
#pragma unroll
        for (int ks = 0; ks < 2; ks++) {
            FragAR a[4];
#pragma unroll
            for (int i = 0; i < 4; i++) {
                wmma::load_matrix_sync(a[i], aT + (m_off + i * 16) * LDKA + ks * 8, LDKA);
#pragma unroll
                for (int e = 0; e < a[i].num_elements; e++) a[i].x[e] = to_tf32(a[i].x[e]);
            }
            if (BNK == 0) {
                FragBR b[4];
#pragma unroll
                for (int j = 0; j < 4; j++) {
                    wmma::load_matrix_sync(b[j], bT + (ks * 8) * LDNB + n_off + j * 16, LDNB);
#pragma unroll
                    for (int e = 0; e < b[j].num_elements; e++) b[j].x[e] = to_tf32(b[j].x[e]);
                }
#pragma unroll
                for (int i = 0; i < 4; i++)
#pragma unroll
                    for (int j = 0; j < 4; j++)
                        wmma::mma_sync(c[i][j], a[i], b[j], c[i][j]);
            } else {
                FragBC b[4];
#pragma unroll
                for (int j = 0; j < 4; j++) {
                    wmma::load_matrix_sync(b[j], bT + (n_off + j * 16) * LDKA + ks * 8, LDKA);
#pragma unroll
                    for (int e = 0; e < b[j].num_elements; e++) b[j].x[e] = to_tf32(b[j].x[e]);
                }
#pragma unroll
                for (int i = 0; i < 4; i++)
#pragma unroll
                    for (int j = 0; j < 4; j++)
                        wmma::mma_sync(c[i][j], a[i], b[j], c[i][j]);
            }
        }
        __syncthreads();
    }

#pragma unroll
    for (int i = 0; i < 4; i++)
#pragma unroll
        for (int j = 0; j < 4; j++) {
            if (relu)
#pragma unroll
                for (int e = 0; e < c[i][j].num_elements; e++)
                    c[i][j].x[e] = fmaxf(c[i][j].x[e], 0.0f);
            float* dst = C + (size_t)(by * 128 + m_off + i * 16) * N
                           + (size_t)bx * 256 + n_off + j * 16;
            wmma::store_matrix_sync(dst, c[i][j], N, wmma::mem_row_major);
        }
}

// ---------------- batched attention score (tf32 wmma) ----------------------------
#define LDA 72
__global__ void __launch_bounds__(256)
k_attn_score(const float* __restrict__ Q, const float* __restrict__ Bm,
             const float* __restrict__ bias, float* __restrict__ Out,
             int jStride, int bOffB, int mode) {
    int i0 = blockIdx.y * 64, j0 = blockIdx.x * 64;
    if (mode == 0) { if (j0 >= i0 + MLEN + 64) return; }
    else           { if (i0 + j0 < 384) return; }

    int g = blockIdx.z;
    int b = g >> 4, h = g & 15;
    const float* Ab = Q + (size_t)b * HD + (size_t)h * DH;
    const float* Bb = Bm + (size_t)b * bOffB + (size_t)h * DH;
    const float* bs = bias + (size_t)h * DH;
    __shared__ float As[64][LDA];
    __shared__ float Bs[64][LDA];
    int tid = threadIdx.x;
    for (int t = tid; t < 1024; t += 256) {
        int row = t >> 4, c4 = (t & 15) << 2;
        float4 a = *(const float4*)(Ab + (size_t)(i0 + row) * (BSZ * HD) + c4);
        As[c4 + 0][row] = to_tf32(a.x + bs[c4 + 0]);
        As[c4 + 1][row] = to_tf32(a.y + bs[c4 + 1]);
        As[c4 + 2][row] = to_tf32(a.z + bs[c4 + 2]);
        As[c4 + 3][row] = to_tf32(a.w + bs[c4 + 3]);
        float4 v = *(const float4*)(Bb + (size_t)(j0 + row) * jStride + c4);
        Bs[c4 + 0][row] = to_tf32(v.x);
        Bs[c4 + 1][row] = to_tf32(v.y);
        Bs[c4 + 2][row] = to_tf32(v.z);
        Bs[c4 + 3][row] = to_tf32(v.w);
    }
    __syncthreads();

    int warp = tid >> 5;
    int mr = warp & 3;
    int nc0 = (warp >> 2) * 2;
    FragC c[2];
    wmma::fill_fragment(c[0], 0.0f);
    wmma::fill_fragment(c[1], 0.0f);
#pragma unroll
    for (int ks = 0; ks < 8; ks++) {
        FragA a;
        wmma::load_matrix_sync(a, &As[ks * 8][mr * 16], LDA);
#pragma unroll
        for (int t = 0; t < 2; t++) {
            FragB bf;
            wmma::load_matrix_sync(bf, &Bs[ks * 8][(nc0 + t) * 16], LDA);
            wmma::mma_sync(c[t], a, bf, c[t]);
        }
    }
    float* O = Out + (size_t)g * QLEN * KLEN;
#pragma unroll
    for (int t = 0; t < 2; t++)
        wmma::store_matrix_sync(O + (size_t)(i0 + mr * 16) * KLEN + j0 + (nc0 + t) * 16,
                                c[t], KLEN, wmma::mem_row_major);
}

// ---------------- fused rel-shift + mask + softmax (row of 1024) -----------------
__global__ void __launch_bounds__(256)
k_softmax(float* __restrict__ AC, const float* __restrict__ BD) {
    int g = blockIdx.y, i = blockIdx.x;
    float* ac = AC + (size_t)g * QLEN * KLEN + (size_t)i * KLEN;
    const float* bd = BD + (size_t)g * QLEN * KLEN + (size_t)i * KLEN;
    int tid = threadIdx.x;
    __shared__ float red[256];
    float s[4];
#pragma unroll
    for (int u = 0; u < 4; u++) {
        int j = tid + u * 256;
        bool valid = (j <= i + MLEN);
        s[u] = valid ? (ac[j] + bd[j + (QLEN - 1) - i]) * ATT_SCALE : NEGV;
    }
    float m = fmaxf(fmaxf(s[0], s[1]), fmaxf(s[2], s[3]));
    red[tid] = m;
    __syncthreads();
    for (int o = 128; o > 0; o >>= 1) {
        if (tid < o) red[tid] = fmaxf(red[tid], red[tid + o]);
        __syncthreads();
    }
    float M = red[0];
    __syncthreads();
    float e[4], sum = 0.f;
#pragma unroll
    for (int u = 0; u < 4; u++) {
        e[u] = (s[u] > 0.5f * NEGV) ? expf(s[u] - M) : 0.f;
        sum += e[u];
    }
    red[tid] = sum;
    __syncthreads();
    for (int o = 128; o > 0; o >>= 1) {
        if (tid < o) red[tid] += red[tid + o];
        __syncthreads();
    }
    float inv = 1.f / red[0];
#pragma unroll
    for (int u = 0; u < 4; u++) ac[tid + u * 256] = e[u] * inv;
}

// ---------------- batched P @ V (tf32 wmma, double-buffered, masked-tile skip) ---
__global__ void __launch_bounds__(256)
k_attn_pv(const float* __restrict__ P, const float* __restrict__ KV,
          float* __restrict__ vec) {
    int g = blockIdx.y;
    int b = g >> 4, h = g & 15;
    int i0 = blockIdx.x * 64;
    const int kt_end = min(KLEN, i0 + 64 + MLEN);
    const float* Pb = P + (size_t)g * QLEN * KLEN;
    const float* Vb = KV + (size_t)b * (2 * HD) + HD + (size_t)h * DH;
    __shared__ float Ps[2][32][LDA];
    __shared__ float Vs[2][32][LDA];
    int tid = threadIdx.x;
    int warp = tid >> 5;
    int mr = warp & 3;
    int nc0 = (warp >> 2) * 2;

    float4 rp[2], rv[2];
    auto ldg = [&](int kt) {
#pragma unroll
        for (int it = 0; it < 2; it++) {
            int idx = tid + it * 256;
            int prow = idx >> 3, pc = (idx & 7) << 2;
            rp[it] = *(const float4*)(Pb + (size_t)(i0 + prow) * KLEN + kt + pc);
            int vrow = idx >> 4, vc = (idx & 15) << 2;
            rv[it] = *(const float4*)(Vb + (size_t)(kt + vrow) * (BSZ * 2 * HD) + vc);
        }
    };
    auto sts = [&](int s) {
#pragma unroll
        for (int it = 0; it < 2; it++) {
            int idx = tid + it * 256;
            int prow = idx >> 3, pc = (idx & 7) << 2;
            Ps[s][pc + 0][prow] = to_tf32(rp[it].x);
            Ps[s][pc + 1][prow] = to_tf32(rp[it].y);
            Ps[s][pc + 2][prow] = to_tf32(rp[it].z);
            Ps[s][pc + 3][prow] = to_tf32(rp[it].w);
            int vrow = idx >> 4, vc = (idx & 15) << 2;
            Vs[s][vrow][vc + 0] = to_tf32(rv[it].x);
            Vs[s][vrow][vc + 1] = to_tf32(rv[it].y);
            Vs[s][vrow][vc + 2] = to_tf32(rv[it].z);
            Vs[s][vrow][vc + 3] = to_tf32(rv[it].w);
        }
    };

    FragC c[2];
    wmma::fill_fragment(c[0], 0.0f);
    wmma::fill_fragment(c[1], 0.0f);

    ldg(0);
    sts(0);
    __syncthreads();
    int s = 0;
    for (int kt = 0; kt < kt_end; kt += 32) {
        bool nxt = (kt + 32) < kt_end;
        if (nxt) ldg(kt + 32);
#pragma unroll
        for (int ks = 0; ks < 4; ks++) {
            FragA a;
            wmma::load_matrix_sync(a, &Ps[s][ks * 8][mr * 16], LDA);
#pragma unroll
            for (int t = 0; t < 2; t++) {
                FragB bf;
                wmma::load_matrix_sync(bf, &Vs[s][ks * 8][(nc0 + t) * 16], LDA);
                wmma::mma_sync(c[t], a, bf, c[t]);
            }
        }
        if (nxt) {
            sts(s ^ 1);
            __syncthreads();
            s ^= 1;
        }
    }
#pragma unroll
    for (int t = 0; t < 2; t++) {
        float* dst = vec + ((size_t)(i0 + mr * 16) * BSZ + b) * HD
                         + (size_t)h * DH + (nc0 + t) * 16;
        wmma::store_matrix_sync(dst, c[t], BSZ * HD, wmma::mem_row_major);
    }
}

// ---------------- layernorm(residual): out = LN(X + R)*g + b ---------------------
__global__ void __launch_bounds__(256)
k_ln(const float* __restrict__ X, const float* __restrict__ R,
     const float* __restrict__ gw, const float* __restrict__ bw,
     float* __restrict__ out) {
    int r = blockIdx.x;
    int tid = threadIdx.x;
    __shared__ float red[256];
    float x[4];
#pragma unroll
    for (int u = 0; u < 4; u++) {
        int d = tid + u * 256;
        x[u] = X[(size_t)r * DM + d] + R[(size_t)r * DM + d];
    }
    float s = x[0] + x[1] + x[2] + x[3];
    red[tid] = s;
    __syncthreads();
    for (int o = 128; o > 0; o >>= 1) {
        if (tid < o) red[tid] += red[tid + o];
        __syncthreads();
    }
    float mu = red[0] * (1.f / DM);
    __syncthreads();
    float v = 0.f;
#pragma unroll
    for (int u = 0; u < 4; u++) { float dd = x[u] - mu; v += dd * dd; }
    red[tid] = v;
    __syncthreads();
    for (int o = 128; o > 0; o >>= 1) {
        if (tid < o) red[tid] += red[tid + o];
        __syncthreads();
    }
    float rstd = rsqrtf(red[0] * (1.f / DM) + 1e-5f);
#pragma unroll
    for (int u = 0; u < 4; u++) {
        int d = tid + u * 256;
        out[(size_t)r * DM + d] = (x[u] - mu) * rstd * gw[d] + bw[d];
    }
}

// ---------------- loss: -(logit[tgt] - logsumexp(row)) ---------------------------
__global__ void __launch_bounds__(256)
k_loss(const float* __restrict__ logits, const int* __restrict__ target,
       float* __restrict__ out) {
    int r = blockIdx.x;
    int tid = threadIdx.x;
    const float* row = logits + (size_t)r * VOCAB;
    float m = -INFINITY, s = 0.f;
    for (int j = tid; j < VOCAB; j += 256) {
        float v = row[j];
        if (v > m) { s = s * expf(m - v) + 1.f; m = v; }
        else s += expf(v - m);
    }
    __shared__ float sm[256], ss[256];
    sm[tid] = m; ss[tid] = s;
    __syncthreads();
    for (int o = 128; o > 0; o >>= 1) {
        if (tid < o) {
            float m1 = sm[tid], m2 = sm[tid + o];
            float M = fmaxf(m1, m2);
            ss[tid] = ss[tid] * expf(m1 - M) + ss[tid + o] * expf(m2 - M);
            sm[tid] = M;
        }
        __syncthreads();
    }
    if (tid == 0) {
        int tgt = target[r];
        out[r] = sm[0] + logf(ss[0]) - row[tgt];
    }
}

// ---------------- host orchestration ---------------------------------------------

static float* sym(const void* s) {
    void* p = nullptr;
    cudaGetSymbolAddress(&p, s);
    return (float*)p;
}

extern "C" void kernel_launch(void* const* d_in, const int* in_sizes, int n_in,
                              void* d_out, int out_size) {
    const int*   data   = (const int*)  d_in[0];
    const int*   target = (const int*)  d_in[1];
    const float* memory = (const float*)d_in[2];
    const float* embW   = (const float*)d_in[3];
    const float* rwb    = (const float*)d_in[4];
    const float* rrb    = (const float*)d_in[5];
    const float* Wq     = (const float*)d_in[6];
    const float* Wkv    = (const float*)d_in[7];
    const float* Wr     = (const float*)d_in[8];
    const float* Wo     = (const float*)d_in[9];
    const float* W1     = (const float*)d_in[10];
    const float* b1     = (const float*)d_in[11];
    const float* W2     = (const float*)d_in[12];
    const float* b2     = (const float*)d_in[13];
    const float* ln1g   = (const float*)d_in[14];
    const float* ln1b   = (const float*)d_in[15];
    const float* ln2g   = (const float*)d_in[16];
    const float* ln2b   = (const float*)d_in[17];

    float* out = (float*)d_out;
    float* loss_out = out;
    float* mems_out = out + (size_t)QLEN * BSZ;

    float* big  = sym(g_big);
    float* ac   = big;
    float* bd   = big + SCORE_ELEMS;
    float* lg   = big;
    float* core = sym(g_core);
    float* xmem = sym(g_xmem);
    float* pos  = sym(g_pos);
    float* qb   = sym(g_q);
    float* kvb  = sym(g_kv);
    float* rkb  = sym(g_rk);
    float* vec  = sym(g_vec);
    float* ffb  = sym(g_ff);
    float* tmp  = sym(g_tmp);

    cudaFuncSetAttribute(k_wgemm<0>, cudaFuncAttributeMaxDynamicSharedMemorySize, WG_SMEM);
    cudaFuncSetAttribute(k_wgemm<1>, cudaFuncAttributeMaxDynamicSharedMemorySize, WG_SMEM);

    const size_t layerF = (size_t)QLEN * BSZ * DM;
    const int copy4 = (int)(layerF / 4);

    const size_t outN = (size_t)out_size;
    const size_t lossN = (size_t)QLEN * BSZ;

    k_embed<<<NROW, 256>>>(data, embW, core);
    k_pos<<<dim3(KLEN, 4), 256>>>(pos);
    if (lossN + layerF <= outN)
        k_copy4<<<copy4 / 256, 256>>>((const float4*)core, (float4*)mems_out, copy4);

    for (int l = 0; l < NLAYER; l++) {
        k_copy4<<<copy4 / 256, 256>>>((const float4*)(memory + (size_t)l * layerF),
                                      (float4*)xmem, copy4);
        k_copy4<<<copy4 / 256, 256>>>((const float4*)core, (float4*)(xmem + layerF), copy4);

        k_wgemm<0><<<dim3(HD / 256, NROW / 128), 256, WG_SMEM>>>(
            core, Wq + (size_t)l * DM * HD, nullptr, qb, NROW, HD, DM, 0);
        k_wgemm<0><<<dim3(2 * HD / 256, KROW / 128), 256, WG_SMEM>>>(
            xmem, Wkv + (size_t)l * DM * 2 * HD, nullptr, kvb, KROW, 2 * HD, DM, 0);
        k_wgemm<0><<<dim3(HD / 256, KLEN / 128), 256, WG_SMEM>>>(
            pos, Wr + (size_t)l * DM * HD, nullptr, rkb, KLEN, HD, DM, 0);

        k_attn_score<<<dim3(KLEN / 64, QLEN / 64, BSZ * NH), 256>>>(
            qb, kvb, rwb, ac, BSZ * 2 * HD, 2 * HD, 0);
        k_attn_score<<<dim3(KLEN / 64, QLEN / 64, BSZ * NH), 256>>>(
            qb, rkb, rrb, bd, HD, 0, 1);

        k_softmax<<<dim3(QLEN, BSZ * NH), 256>>>(ac, bd);
        k_attn_pv<<<dim3(QLEN / 64, BSZ * NH), 256>>>(ac, kvb, vec);

        k_wgemm<0><<<dim3(DM / 256, NROW / 128), 256, WG_SMEM>>>(
            vec, Wo + (size_t)l * HD * DM, nullptr, tmp, NROW, DM, HD, 0);
        k_ln<<<NROW, 256>>>(core, tmp, ln1g + (size_t)l * DM, ln1b + (size_t)l * DM, core);

        k_wgemm<0><<<dim3(DI / 256, NROW / 128), 256, WG_SMEM>>>(
            core, W1 + (size_t)l * DM * DI, b1 + (size_t)l * DI, ffb, NROW, DI, DM, 1);
        k_wgemm<0><<<dim3(DM / 256, NROW / 128), 256, WG_SMEM>>>(
            ffb, W2 + (size_t)l * DI * DM, b2 + (size_t)l * DM, tmp, NROW, DM, DI, 0);
        k_ln<<<NROW, 256>>>(core, tmp, ln2g + (size_t)l * DM, ln2b + (size_t)l * DM, core);

        if (l < NLAYER - 1 && lossN + (size_t)(l + 2) * layerF <= outN)
            k_copy4<<<copy4 / 256, 256>>>((const float4*)core,
                                          (float4*)(mems_out + (size_t)(l + 1) * layerF), copy4);
    }

    k_wgemm<1><<<dim3(VOCAB / 256, NROW / 128), 256, WG_SMEM>>>(
        core, embW, nullptr, lg, NROW, VOCAB, DM, 0);
    k_loss<<<NROW, 256>>>(lg, target, loss_out);
}

// round 12
// speedup vs baseline: 1.7634x; 1.7634x over previous
#include <cuda_runtime.h>
#include <cuda_fp16.h>
#include <math.h>
#include <stdint.h>
#include <mma.h>

using namespace nvcuda;

#define QLEN 512
#define MLEN 512
#define KLEN 1024          // QLEN + MLEN
#define BSZ 8
#define NH 16
#define DH 64
#define DM 1024
#define HD 1024            // NH*DH
#define DI 4096
#define NLAYER 6
#define VOCAB 32000
#define ATT_SCALE 0.125f   // 1/sqrt(64)
#define NEGV -1e30f

#define NROW (QLEN*BSZ)        // 4096
#define KROW (KLEN*BSZ)        // 8192

// ---------------- scratch (static device globals; no runtime allocation) ---------
#define SCORE_ELEMS ((size_t)BSZ*NH*QLEN*KLEN)            // 67,108,864 floats
#define LOGIT_ELEMS ((size_t)NROW*VOCAB)                  // 131,072,000 floats
#define BIG_ELEMS   (2*SCORE_ELEMS)
static_assert(BIG_ELEMS >= LOGIT_ELEMS, "g_big must also fit logits");
__device__ float g_big   [BIG_ELEMS];
__device__ float g_core  [(size_t)NROW*DM];
__device__ float g_xmem  [(size_t)KROW*DM];
__device__ float g_pos   [(size_t)KLEN*DM];
__device__ float g_q     [(size_t)NROW*HD];
__device__ float g_kv    [(size_t)KROW*2*HD];
__device__ float g_rk    [(size_t)KLEN*HD];
__device__ float g_vec   [(size_t)NROW*HD];
__device__ float g_ff    [(size_t)NROW*DI];
__device__ float g_tmp   [(size_t)NROW*DM];

__device__ __forceinline__ float to_tf32(float x) {
    float y;
    asm("cvt.rna.tf32.f32 %0, %1;" : "=f"(y) : "f"(x));
    return y;
}

typedef wmma::fragment<wmma::matrix_a, 16, 16, 8, wmma::precision::tf32, wmma::col_major> FragA;
typedef wmma::fragment<wmma::matrix_b, 16, 16, 8, wmma::precision::tf32, wmma::row_major> FragB;
typedef wmma::fragment<wmma::accumulator, 16, 16, 8, float> FragC;

typedef wmma::fragment<wmma::matrix_a, 16, 16, 16, __half, wmma::col_major> HFragA;
typedef wmma::fragment<wmma::matrix_b, 16, 16, 16, __half, wmma::row_major> HFragB;
typedef wmma::fragment<wmma::accumulator, 16, 16, 16, float> HFragC;

// ---------------- small utility kernels ----------------

__global__ void k_copy4(const float4* __restrict__ src, float4* __restrict__ dst, int n4) {
    int i = blockIdx.x * blockDim.x + threadIdx.x;
    if (i < n4) dst[i] = src[i];
}

__global__ void k_embed(const int* __restrict__ data, const float* __restrict__ embW,
                        float* __restrict__ core) {
    int r = blockIdx.x;
    int tok = data[r];
    const float4* s = (const float4*)(embW + (size_t)tok * DM);
    float4* d = (float4*)(core + (size_t)r * DM);
    d[threadIdx.x] = s[threadIdx.x];
}

__global__ void k_pos(float* __restrict__ pos) {
    int p = blockIdx.x;
    int d = blockIdx.y * 256 + threadIdx.x;
    float ps = (float)(KLEN - 1 - p);
    int idx = (d < DM/2) ? d : (d - DM/2);
    float e = (float)(2 * idx) / (float)DM;
    float inv = powf(10000.0f, -e);
    float v = ps * inv;
    pos[(size_t)p * DM + d] = (d < DM/2) ? sinf(v) : cosf(v);
}

// ---------------- fp16 WMMA GEMM, 128x256 tile, BK=16, double-buffered -----------
// C[M,N] = A[M,K] @ B (+bias)(+relu).  BNK==0: B is [K][N];  BNK==1: B is [N][K].
// Inputs converted fp32->fp16 (same 10-bit mantissa as tf32); fp32 accumulate.
#define LDTA 136
#define LDTB 264
#define A_ST_H (16 * LDTA)                 // halves per A stage (2176)
#define B_ST_H (16 * LDTB)                 // halves per B stage (4224)
#define WG_SMEM (2*A_ST_H*2 + 2*B_ST_H*2 + 16*LDTB*4)   // 42,496 bytes

template<int BNK>
__global__ void __launch_bounds__(256, 1)
k_wgemm(const float* __restrict__ A, const float* __restrict__ B,
        const float* __restrict__ bias, float* __restrict__ C,
        int M, int N, int K, int relu) {
    extern __shared__ char dsmc[];
    __half* As0   = (__half*)dsmc;                             // [2][16][LDTA]
    __half* Bs0   = (__half*)(dsmc + 2 * A_ST_H * 2);          // [2][16][LDTB]
    float*  biasf = (float*) (dsmc + 2 * A_ST_H * 2 + 2 * B_ST_H * 2);

    int tid = threadIdx.x;
    int bx = blockIdx.x, by = blockIdx.y;
    int warp = tid >> 5;
    int m_off = (warp >> 2) * 64;      // 0 or 64
    int n_off = (warp & 3) * 64;       // 0,64,128,192

    const float* Abase = A + (size_t)by * 128 * K;

    float4 ra[2], rb[4];
    auto ldg = [&](int k0) {
#pragma unroll
        for (int it = 0; it < 2; it++) {
            int idx = tid + it * 256;
            int row = idx >> 2, kq = (idx & 3) << 2;
            ra[it] = *(const float4*)(Abase + (size_t)row * K + k0 + kq);
        }
#pragma unroll
        for (int it = 0; it < 4; it++) {
            int idx = tid + it * 256;
            if (BNK == 0) {
                int row = idx >> 6, nc = (idx & 63) << 2;
                rb[it] = *(const float4*)(B + (size_t)(k0 + row) * N + (size_t)bx * 256 + nc);
            } else {
                int row = idx >> 2, kq = (idx & 3) << 2;
                rb[it] = *(const float4*)(B + (size_t)(bx * 256 + row) * K + k0 + kq);
            }
        }
    };
    auto sts = [&](int s) {
        __half* As = As0 + s * A_ST_H;
        __half* Bs = Bs0 + s * B_ST_H;
#pragma unroll
        for (int it = 0; it < 2; it++) {
            int idx = tid + it * 256;
            int row = idx >> 2, kq = (idx & 3) << 2;
            As[(kq + 0) * LDTA + row] = __float2half_rn(ra[it].x);
            As[(kq + 1) * LDTA + row] = __float2half_rn(ra[it].y);
            As[(kq + 2) * LDTA + row] = __float2half_rn(ra[it].z);
            As[(kq + 3) * LDTA + row] = __float2half_rn(ra[it].w);
        }
#pragma unroll
        for (int it = 0; it < 4; it++) {
            int idx = tid + it * 256;
            if (BNK == 0) {
                int row = idx >> 6, nc = (idx & 63) << 2;
                *(__half2*)&Bs[row * LDTB + nc]     = __floats2half2_rn(rb[it].x, rb[it].y);
                *(__half2*)&Bs[row * LDTB + nc + 2] = __floats2half2_rn(rb[it].z, rb[it].w);
            } else {
                int row = idx >> 2, kq = (idx & 3) << 2;
                Bs[(kq + 0) * LDTB + row] = __float2half_rn(rb[it].x);
                Bs[(kq + 1) * LDTB + row] = __float2half_rn(rb[it].y);
                Bs[(kq + 2) * LDTB + row] = __float2half_rn(rb[it].z);
                Bs[(kq + 3) * LDTB + row] = __float2half_rn(rb[it].w);
            }
        }
    };

    if (bias) {
        for (int idx = tid; idx < 16 * 256; idx += 256) {
            int r = idx >> 8, n = idx & 255;
            biasf[r * LDTB + n] = bias[(size_t)bx * 256 + n];
        }
    }

    ldg(0);
    sts(0);
    __syncthreads();

    HFragC c[4][4];
#pragma unroll
    for (int i = 0; i < 4; i++)
#pragma unroll
        for (int j = 0; j < 4; j++) {
            if (bias) wmma::load_matrix_sync(c[i][j], biasf + n_off + j * 16, LDTB,
                                             wmma::mem_row_major);
            else      wmma::fill_fragment(c[i][j], 0.0f);
        }

    int s = 0;
    for (int k0 = 0; k0 < K; k0 += 16) {
        bool nxt = (k0 + 16) < K;
        if (nxt) ldg(k0 + 16);

        const __half* As = As0 + s * A_ST_H;
        const __half* Bs = Bs0 + s * B_ST_H;
        HFragA a[4];
        HFragB b[4];
#pragma unroll
        for (int i = 0; i < 4; i++)
            wmma::load_matrix_sync(a[i], As + m_off + i * 16, LDTA);
#pragma unroll
        for (int j = 0; j < 4; j++)
            wmma::load_matrix_sync(b[j], Bs + n_off + j * 16, LDTB);
#pragma unroll
        for (int i = 0; i < 4; i++)
#pragma unroll
            for (int j = 0; j < 4; j++)
                wmma::mma_sync(c[i][j], a[i], b[j], c[i][j]);

        if (nxt) {
            sts(s ^ 1);
            __syncthreads();
            s ^= 1;
        }
    }

#pragma unroll
    for (int i = 0; i < 4; i++)
#pragma unroll
        for (int j = 0; j < 4; j++) {
            if (relu)
#pragma unroll
                for (int e = 0; e < c[i][j].num_elements; e++)
                    c[i][j].x[e] = fmaxf(c[i][j].x[e], 0.0f);
            float* dst = C + (size_t)(by * 128 + m_off + i * 16) * N
                           + (size_t)bx * 256 + n_off + j * 16;
            wmma::store_matrix_sync(dst, c[i][j], N, wmma::mem_row_major);
        }
}

// ---------------- batched attention score (tf32 wmma) ----------------------------
#define LDA 72
__global__ void __launch_bounds__(256)
k_attn_score(const float* __restrict__ Q, const float* __restrict__ Bm,
             const float* __restrict__ bias, float* __restrict__ Out,
             int jStride, int bOffB, int mode) {
    int i0 = blockIdx.y * 64, j0 = blockIdx.x * 64;
    if (mode == 0) { if (j0 >= i0 + MLEN + 64) return; }
    else           { if (i0 + j0 < 384) return; }

    int g = blockIdx.z;
    int b = g >> 4, h = g & 15;
    const float* Ab = Q + (size_t)b * HD + (size_t)h * DH;
    const float* Bb = Bm + (size_t)b * bOffB + (size_t)h * DH;
    const float* bs = bias + (size_t)h * DH;
    __shared__ float As[64][LDA];
    __shared__ float Bs[64][LDA];
    int tid = threadIdx.x;
    for (int t = tid; t < 1024; t += 256) {
        int row = t >> 4, c4 = (t & 15) << 2;
        float4 a = *(const float4*)(Ab + (size_t)(i0 + row) * (BSZ * HD) + c4);
        As[c4 + 0][row] = to_tf32(a.x + bs[c4 + 0]);
        As[c4 + 1][row] = to_tf32(a.y + bs[c4 + 1]);
        As[c4 + 2][row] = to_tf32(a.z + bs[c4 + 2]);
        As[c4 + 3][row] = to_tf32(a.w + bs[c4 + 3]);
        float4 v = *(const float4*)(Bb + (size_t)(j0 + row) * jStride + c4);
        Bs[c4 + 0][row] = to_tf32(v.x);
        Bs[c4 + 1][row] = to_tf32(v.y);
        Bs[c4 + 2][row] = to_tf32(v.z);
        Bs[c4 + 3][row] = to_tf32(v.w);
    }
    __syncthreads();

    int warp = tid >> 5;
    int mr = warp & 3;
    int nc0 = (warp >> 2) * 2;
    FragC c[2];
    wmma::fill_fragment(c[0], 0.0f);
    wmma::fill_fragment(c[1], 0.0f);
#pragma unroll
    for (int ks = 0; ks < 8; ks++) {
        FragA a;
        wmma::load_matrix_sync(a, &As[ks * 8][mr * 16], LDA);
#pragma unroll
        for (int t = 0; t < 2; t++) {
            FragB bf;
            wmma::load_matrix_sync(bf, &Bs[ks * 8][(nc0 + t) * 16], LDA);
            wmma::mma_sync(c[t], a, bf, c[t]);
        }
    }
    float* O = Out + (size_t)g * QLEN * KLEN;
#pragma unroll
    for (int t = 0; t < 2; t++)
        wmma::store_matrix_sync(O + (size_t)(i0 + mr * 16) * KLEN + j0 + (nc0 + t) * 16,
                                c[t], KLEN, wmma::mem_row_major);
}

// ---------------- fused rel-shift + mask + softmax (row of 1024) -----------------
__global__ void __launch_bounds__(256)
k_softmax(float* __restrict__ AC, const float* __restrict__ BD) {
    int g = blockIdx.y, i = blockIdx.x;
    float* ac = AC + (size_t)g * QLEN * KLEN + (size_t)i * KLEN;
    const float* bd = BD + (size_t)g * QLEN * KLEN + (size_t)i * KLEN;
    int tid = threadIdx.x;
    __shared__ float red[256];
    float s[4];
#pragma unroll
    for (int u = 0; u < 4; u++) {
        int j = tid + u * 256;
        bool valid = (j <= i + MLEN);
        s[u] = valid ? (ac[j] + bd[j + (QLEN - 1) - i]) * ATT_SCALE : NEGV;
    }
    float m = fmaxf(fmaxf(s[0], s[1]), fmaxf(s[2], s[3]));
    red[tid] = m;
    __syncthreads();
    for (int o = 128; o > 0; o >>= 1) {
        if (tid < o) red[tid] = fmaxf(red[tid], red[tid + o]);
        __syncthreads();
    }
    float M = red[0];
    __syncthreads();
    float e[4], sum = 0.f;
#pragma unroll
    for (int u = 0; u < 4; u++) {
        e[u] = (s[u] > 0.5f * NEGV) ? expf(s[u] - M) : 0.f;
        sum += e[u];
    }
    red[tid] = sum;
    __syncthreads();
    for (int o = 128; o > 0; o >>= 1) {
        if (tid < o) red[tid] += red[tid + o];
        __syncthreads();
    }
    float inv = 1.f / red[0];
#pragma unroll
    for (int u = 0; u < 4; u++) ac[tid + u * 256] = e[u] * inv;
}

// ---------------- batched P @ V (tf32 wmma, double-buffered, masked-tile skip) ---
__global__ void __launch_bounds__(256)
k_attn_pv(const float* __restrict__ P, const float* __restrict__ KV,
          float* __restrict__ vec) {
    int g = blockIdx.y;
    int b = g >> 4, h = g & 15;
    int i0 = blockIdx.x * 64;
    const int kt_end = min(KLEN, i0 + 64 + MLEN);
    const float* Pb = P + (size_t)g * QLEN * KLEN;
    const float* Vb = KV + (size_t)b * (2 * HD) + HD + (size_t)h * DH;
    __shared__ float Ps[2][32][LDA];
    __shared__ float Vs[2][32][LDA];
    int tid = threadIdx.x;
    int warp = tid >> 5;
    int mr = warp & 3;
    int nc0 = (warp >> 2) * 2;

    float4 rp[2], rv[2];
    auto ldg = [&](int kt) {
#pragma unroll
        for (int it = 0; it < 2; it++) {
            int idx = tid + it * 256;
            int prow = idx >> 3, pc = (idx & 7) << 2;
            rp[it] = *(const float4*)(Pb + (size_t)(i0 + prow) * KLEN + kt + pc);
            int vrow = idx >> 4, vc = (idx & 15) << 2;
            rv[it] = *(const float4*)(Vb + (size_t)(kt + vrow) * (BSZ * 2 * HD) + vc);
        }
    };
    auto sts = [&](int s) {
#pragma unroll
        for (int it = 0; it < 2; it++) {
            int idx = tid + it * 256;
            int prow = idx >> 3, pc = (idx & 7) << 2;
            Ps[s][pc + 0][prow] = to_tf32(rp[it].x);
            Ps[s][pc + 1][prow] = to_tf32(rp[it].y);
            Ps[s][pc + 2][prow] = to_tf32(rp[it].z);
            Ps[s][pc + 3][prow] = to_tf32(rp[it].w);
            int vrow = idx >> 4, vc = (idx & 15) << 2;
            Vs[s][vrow][vc + 0] = to_tf32(rv[it].x);
            Vs[s][vrow][vc + 1] = to_tf32(rv[it].y);
            Vs[s][vrow][vc + 2] = to_tf32(rv[it].z);
            Vs[s][vrow][vc + 3] = to_tf32(rv[it].w);
        }
    };

    FragC c[2];
    wmma::fill_fragment(c[0], 0.0f);
    wmma::fill_fragment(c[1], 0.0f);

    ldg(0);
    sts(0);
    __syncthreads();
    int s = 0;
    for (int kt = 0; kt < kt_end; kt += 32) {
        bool nxt = (kt + 32) < kt_end;
        if (nxt) ldg(kt + 32);
#pragma unroll
        for (int ks = 0; ks < 4; ks++) {
            FragA a;
            wmma::load_matrix_sync(a, &Ps[s][ks * 8][mr * 16], LDA);
#pragma unroll
            for (int t = 0; t < 2; t++) {
                FragB bf;
                wmma::load_matrix_sync(bf, &Vs[s][ks * 8][(nc0 + t) * 16], LDA);
                wmma::mma_sync(c[t], a, bf, c[t]);
            }
        }
        if (nxt) {
            sts(s ^ 1);
            __syncthreads();
            s ^= 1;
        }
    }
#pragma unroll
    for (int t = 0; t < 2; t++) {
        float* dst = vec + ((size_t)(i0 + mr * 16) * BSZ + b) * HD
                         + (size_t)h * DH + (nc0 + t) * 16;
        wmma::store_matrix_sync(dst, c[t], BSZ * HD, wmma::mem_row_major);
    }
}

// ---------------- layernorm(residual): out = LN(X + R)*g + b ---------------------
__global__ void __launch_bounds__(256)
k_ln(const float* __restrict__ X, const float* __restrict__ R,
     const float* __restrict__ gw, const float* __restrict__ bw,
     float* __restrict__ out) {
    int r = blockIdx.x;
    int tid = threadIdx.x;
    __shared__ float red[256];
    float x[4];
#pragma unroll
    for (int u = 0; u < 4; u++) {
        int d = tid + u * 256;
        x[u] = X[(size_t)r * DM + d] + R[(size_t)r * DM + d];
    }
    float s = x[0] + x[1] + x[2] + x[3];
    red[tid] = s;
    __syncthreads();
    for (int o = 128; o > 0; o >>= 1) {
        if (tid < o) red[tid] += red[tid + o];
        __syncthreads();
    }
    float mu = red[0] * (1.f / DM);
    __syncthreads();
    float v = 0.f;
#pragma unroll
    for (int u = 0; u < 4; u++) { float dd = x[u] - mu; v += dd * dd; }
    red[tid] = v;
    __syncthreads();
    for (int o = 128; o > 0; o >>= 1) {
        if (tid < o) red[tid] += red[tid + o];
        __syncthreads();
    }
    float rstd = rsqrtf(red[0] * (1.f / DM) + 1e-5f);
#pragma unroll
    for (int u = 0; u < 4; u++) {
        int d = tid + u * 256;
        out[(size_t)r * DM + d] = (x[u] - mu) * rstd * gw[d] + bw[d];
    }
}

// ---------------- loss: -(logit[tgt] - logsumexp(row)) ---------------------------
__global__ void __launch_bounds__(256)
k_loss(const float* __restrict__ logits, const int* __restrict__ target,
       float* __restrict__ out) {
    int r = blockIdx.x;
    int tid = threadIdx.x;
    const float* row = logits + (size_t)r * VOCAB;
    float m = -INFINITY, s = 0.f;
    for (int j = tid; j < VOCAB; j += 256) {
        float v = row[j];
        if (v > m) { s = s * expf(m - v) + 1.f; m = v; }
        else s += expf(v - m);
    }
    __shared__ float sm[256], ss[256];
    sm[tid] = m; ss[tid] = s;
    __syncthreads();
    for (int o = 128; o > 0; o >>= 1) {
        if (tid < o) {
            float m1 = sm[tid], m2 = sm[tid + o];
            float M = fmaxf(m1, m2);
            ss[tid] = ss[tid] * expf(m1 - M) + ss[tid + o] * expf(m2 - M);
            sm[tid] = M;
        }
        __syncthreads();
    }
    if (tid == 0) {
        int tgt = target[r];
        out[r] = sm[0] + logf(ss[0]) - row[tgt];
    }
}

// ---------------- host orchestration ---------------------------------------------

static float* sym(const void* s) {
    void* p = nullptr;
    cudaGetSymbolAddress(&p, s);
    return (float*)p;
}

extern "C" void kernel_launch(void* const* d_in, const int* in_sizes, int n_in,
                              void* d_out, int out_size) {
    const int*   data   = (const int*)  d_in[0];
    const int*   target = (const int*)  d_in[1];
    const float* memory = (const float*)d_in[2];
    const float* embW   = (const float*)d_in[3];
    const float* rwb    = (const float*)d_in[4];
    const float* rrb    = (const float*)d_in[5];
    const float* Wq     = (const float*)d_in[6];
    const float* Wkv    = (const float*)d_in[7];
    const float* Wr     = (const float*)d_in[8];
    const float* Wo     = (const float*)d_in[9];
    const float* W1     = (const float*)d_in[10];
    const float* b1     = (const float*)d_in[11];
    const float* W2     = (const float*)d_in[12];
    const float* b2     = (const float*)d_in[13];
    const float* ln1g   = (const float*)d_in[14];
    const float* ln1b   = (const float*)d_in[15];
    const float* ln2g   = (const float*)d_in[16];
    const float* ln2b   = (const float*)d_in[17];

    float* out = (float*)d_out;
    float* loss_out = out;
    float* mems_out = out + (size_t)QLEN * BSZ;

    float* big  = sym(g_big);
    float* ac   = big;
    float* bd   = big + SCORE_ELEMS;
    float* lg   = big;
    float* core = sym(g_core);
    float* xmem = sym(g_xmem);
    float* pos  = sym(g_pos);
    float* qb   = sym(g_q);
    float* kvb  = sym(g_kv);
    float* rkb  = sym(g_rk);
    float* vec  = sym(g_vec);
    float* ffb  = sym(g_ff);
    float* tmp  = sym(g_tmp);

    cudaFuncSetAttribute(k_wgemm<0>, cudaFuncAttributeMaxDynamicSharedMemorySize, WG_SMEM);
    cudaFuncSetAttribute(k_wgemm<1>, cudaFuncAttributeMaxDynamicSharedMemorySize, WG_SMEM);

    const size_t layerF = (size_t)QLEN * BSZ * DM;
    const int copy4 = (int)(layerF / 4);

    const size_t outN = (size_t)out_size;
    const size_t lossN = (size_t)QLEN * BSZ;

    k_embed<<<NROW, 256>>>(data, embW, core);
    k_pos<<<dim3(KLEN, 4), 256>>>(pos);
    if (lossN + layerF <= outN)
        k_copy4<<<copy4 / 256, 256>>>((const float4*)core, (float4*)mems_out, copy4);

    for (int l = 0; l < NLAYER; l++) {
        k_copy4<<<copy4 / 256, 256>>>((const float4*)(memory + (size_t)l * layerF),
                                      (float4*)xmem, copy4);
        k_copy4<<<copy4 / 256, 256>>>((const float4*)core, (float4*)(xmem + layerF), copy4);

        k_wgemm<0><<<dim3(HD / 256, NROW / 128), 256, WG_SMEM>>>(
            core, Wq + (size_t)l * DM * HD, nullptr, qb, NROW, HD, DM, 0);
        k_wgemm<0><<<dim3(2 * HD / 256, KROW / 128), 256, WG_SMEM>>>(
            xmem, Wkv + (size_t)l * DM * 2 * HD, nullptr, kvb, KROW, 2 * HD, DM, 0);
        k_wgemm<0><<<dim3(HD / 256, KLEN / 128), 256, WG_SMEM>>>(
            pos, Wr + (size_t)l * DM * HD, nullptr, rkb, KLEN, HD, DM, 0);

        k_attn_score<<<dim3(KLEN / 64, QLEN / 64, BSZ * NH), 256>>>(
            qb, kvb, rwb, ac, BSZ * 2 * HD, 2 * HD, 0);
        k_attn_score<<<dim3(KLEN / 64, QLEN / 64, BSZ * NH), 256>>>(
            qb, rkb, rrb, bd, HD, 0, 1);

        k_softmax<<<dim3(QLEN, BSZ * NH), 256>>>(ac, bd);
        k_attn_pv<<<dim3(QLEN / 64, BSZ * NH), 256>>>(ac, kvb, vec);

        k_wgemm<0><<<dim3(DM / 256, NROW / 128), 256, WG_SMEM>>>(
            vec, Wo + (size_t)l * HD * DM, nullptr, tmp, NROW, DM, HD, 0);
        k_ln<<<NROW, 256>>>(core, tmp, ln1g + (size_t)l * DM, ln1b + (size_t)l * DM, core);

        k_wgemm<0><<<dim3(DI / 256, NROW / 128), 256, WG_SMEM>>>(
            core, W1 + (size_t)l * DM * DI, b1 + (size_t)l * DI, ffb, NROW, DI, DM, 1);
        k_wgemm<0><<<dim3(DM / 256, NROW / 128), 256, WG_SMEM>>>(
            ffb, W2 + (size_t)l * DI * DM, b2 + (size_t)l * DM, tmp, NROW, DM, DI, 0);
        k_ln<<<NROW, 256>>>(core, tmp, ln2g + (size_t)l * DM, ln2b + (size_t)l * DM, core);

        if (l < NLAYER - 1 && lossN + (size_t)(l + 2) * layerF <= outN)
            k_copy4<<<copy4 / 256, 256>>>((const float4*)core,
                                          (float4*)(mems_out + (size_t)(l + 1) * layerF), copy4);
    }

    k_wgemm<1><<<dim3(VOCAB / 256, NROW / 128), 256, WG_SMEM>>>(
        core, embW, nullptr, lg, NROW, VOCAB, DM, 0);
    k_loss<<<NROW, 256>>>(lg, target, loss_out);
}

// round 13
// speedup vs baseline: 2.1017x; 1.1919x over previous
#include <cuda_runtime.h>
#include <cuda_fp16.h>
#include <math.h>
#include <stdint.h>
#include <mma.h>

using namespace nvcuda;

#define QLEN 512
#define MLEN 512
#define KLEN 1024          // QLEN + MLEN
#define BSZ 8
#define NH 16
#define DH 64
#define DM 1024
#define HD 1024            // NH*DH
#define DI 4096
#define NLAYER 6
#define VOCAB 32000
#define ATT_SCALE 0.125f   // 1/sqrt(64)
#define NEGV -1e30f

#define NROW (QLEN*BSZ)        // 4096
#define KROW (KLEN*BSZ)        // 8192

// ---------------- scratch (static device globals; no runtime allocation) ---------
#define SCORE_ELEMS ((size_t)BSZ*NH*QLEN*KLEN)            // 67,108,864
#define LOGIT_ELEMS ((size_t)NROW*VOCAB)                  // 131,072,000 floats
#define BIG_ELEMS   (2*SCORE_ELEMS)
static_assert(BIG_ELEMS >= LOGIT_ELEMS, "g_big must also fit logits");
// scores live as __half (2 x SCORE_ELEMS halves = 268 MB) inside g_big;
// logits reuse the same buffer as float later.
__device__ float g_big   [BIG_ELEMS];
__device__ float g_core  [(size_t)NROW*DM];
__device__ float g_xmem  [(size_t)KROW*DM];
__device__ float g_pos   [(size_t)KLEN*DM];
__device__ float g_q     [(size_t)NROW*HD];
__device__ float g_kv    [(size_t)KROW*2*HD];
__device__ float g_rk    [(size_t)KLEN*HD];
__device__ float g_vec   [(size_t)NROW*HD];
__device__ float g_ff    [(size_t)NROW*DI];
__device__ float g_tmp   [(size_t)NROW*DM];

typedef wmma::fragment<wmma::matrix_a, 16, 16, 16, __half, wmma::col_major> HFragA;
typedef wmma::fragment<wmma::matrix_b, 16, 16, 16, __half, wmma::row_major> HFragB;
typedef wmma::fragment<wmma::accumulator, 16, 16, 16, float> HFragC;

// ---------------- small utility kernels ----------------

__global__ void k_copy4(const float4* __restrict__ src, float4* __restrict__ dst, int n4) {
    int i = blockIdx.x * blockDim.x + threadIdx.x;
    if (i < n4) dst[i] = src[i];
}

__global__ void k_embed(const int* __restrict__ data, const float* __restrict__ embW,
                        float* __restrict__ core) {
    int r = blockIdx.x;
    int tok = data[r];
    const float4* s = (const float4*)(embW + (size_t)tok * DM);
    float4* d = (float4*)(core + (size_t)r * DM);
    d[threadIdx.x] = s[threadIdx.x];
}

__global__ void k_pos(float* __restrict__ pos) {
    int p = blockIdx.x;
    int d = blockIdx.y * 256 + threadIdx.x;
    float ps = (float)(KLEN - 1 - p);
    int idx = (d < DM/2) ? d : (d - DM/2);
    float e = (float)(2 * idx) / (float)DM;
    float inv = powf(10000.0f, -e);
    float v = ps * inv;
    pos[(size_t)p * DM + d] = (d < DM/2) ? sinf(v) : cosf(v);
}

// ---------------- fp16 WMMA GEMM, 128x256 tile, BK=16, double-buffered (R12) -----
#define LDTA 136
#define LDTB 264
#define A_ST_H (16 * LDTA)
#define B_ST_H (16 * LDTB)
#define WG_SMEM (2*A_ST_H*2 + 2*B_ST_H*2 + 16*LDTB*4)   // 42,496 bytes

template<int BNK>
__global__ void __launch_bounds__(256, 1)
k_wgemm(const float* __restrict__ A, const float* __restrict__ B,
        const float* __restrict__ bias, float* __restrict__ C,
        int M, int N, int K, int relu) {
    extern __shared__ char dsmc[];
    __half* As0   = (__half*)dsmc;
    __half* Bs0   = (__half*)(dsmc + 2 * A_ST_H * 2);
    float*  biasf = (float*) (dsmc + 2 * A_ST_H * 2 + 2 * B_ST_H * 2);

    int tid = threadIdx.x;
    int bx = blockIdx.x, by = blockIdx.y;
    int warp = tid >> 5;
    int m_off = (warp >> 2) * 64;
    int n_off = (warp & 3) * 64;

    const float* Abase = A + (size_t)by * 128 * K;

    float4 ra[2], rb[4];
    auto ldg = [&](int k0) {
#pragma unroll
        for (int it = 0; it < 2; it++) {
            int idx = tid + it * 256;
            int row = idx >> 2, kq = (idx & 3) << 2;
            ra[it] = *(const float4*)(Abase + (size_t)row * K + k0 + kq);
        }
#pragma unroll
        for (int it = 0; it < 4; it++) {
            int idx = tid + it * 256;
            if (BNK == 0) {
                int row = idx >> 6, nc = (idx & 63) << 2;
                rb[it] = *(const float4*)(B + (size_t)(k0 + row) * N + (size_t)bx * 256 + nc);
            } else {
                int row = idx >> 2, kq = (idx & 3) << 2;
                rb[it] = *(const float4*)(B + (size_t)(bx * 256 + row) * K + k0 + kq);
            }
        }
    };
    auto sts = [&](int s) {
        __half* As = As0 + s * A_ST_H;
        __half* Bs = Bs0 + s * B_ST_H;
#pragma unroll
        for (int it = 0; it < 2; it++) {
            int idx = tid + it * 256;
            int row = idx >> 2, kq = (idx & 3) << 2;
            As[(kq + 0) * LDTA + row] = __float2half_rn(ra[it].x);
            As[(kq + 1) * LDTA + row] = __float2half_rn(ra[it].y);
            As[(kq + 2) * LDTA + row] = __float2half_rn(ra[it].z);
            As[(kq + 3) * LDTA + row] = __float2half_rn(ra[it].w);
        }
#pragma unroll
        for (int it = 0; it < 4; it++) {
            int idx = tid + it * 256;
            if (BNK == 0) {
                int row = idx >> 6, nc = (idx & 63) << 2;
                *(__half2*)&Bs[row * LDTB + nc]     = __floats2half2_rn(rb[it].x, rb[it].y);
                *(__half2*)&Bs[row * LDTB + nc + 2] = __floats2half2_rn(rb[it].z, rb[it].w);
            } else {
                int row = idx >> 2, kq = (idx & 3) << 2;
                Bs[(kq + 0) * LDTB + row] = __float2half_rn(rb[it].x);
                Bs[(kq + 1) * LDTB + row] = __float2half_rn(rb[it].y);
                Bs[(kq + 2) * LDTB + row] = __float2half_rn(rb[it].z);
                Bs[(kq + 3) * LDTB + row] = __float2half_rn(rb[it].w);
            }
        }
    };

    if (bias) {
        for (int idx = tid; idx < 16 * 256; idx += 256) {
            int r = idx >> 8, n = idx & 255;
            biasf[r * LDTB + n] = bias[(size_t)bx * 256 + n];
        }
    }

    ldg(0);
    sts(0);
    __syncthreads();

    HFragC c[4][4];
#pragma unroll
    for (int i = 0; i < 4; i++)
#pragma unroll
        for (int j = 0; j < 4; j++) {
            if (bias) wmma::load_matrix_sync(c[i][j], biasf + n_off + j * 16, LDTB,
                                             wmma::mem_row_major);
            else      wmma::fill_fragment(c[i][j], 0.0f);
        }

    int s = 0;
    for (int k0 = 0; k0 < K; k0 += 16) {
        bool nxt = (k0 + 16) < K;
        if (nxt) ldg(k0 + 16);

        const __half* As = As0 + s * A_ST_H;
        const __half* Bs = Bs0 + s * B_ST_H;
        HFragA a[4];
        HFragB b[4];
#pragma unroll
        for (int i = 0; i < 4; i++)
            wmma::load_matrix_sync(a[i], As + m_off + i * 16, LDTA);
#pragma unroll
        for (int j = 0; j < 4; j++)
            wmma::load_matrix_sync(b[j], Bs + n_off + j * 16, LDTB);
#pragma unroll
        for (int i = 0; i < 4; i++)
#pragma unroll
            for (int j = 0; j < 4; j++)
                wmma::mma_sync(c[i][j], a[i], b[j], c[i][j]);

        if (nxt) {
            sts(s ^ 1);
            __syncthreads();
            s ^= 1;
        }
    }

#pragma unroll
    for (int i = 0; i < 4; i++)
#pragma unroll
        for (int j = 0; j < 4; j++) {
            if (relu)
#pragma unroll
                for (int e = 0; e < c[i][j].num_elements; e++)
                    c[i][j].x[e] = fmaxf(c[i][j].x[e], 0.0f);
            float* dst = C + (size_t)(by * 128 + m_off + i * 16) * N
                           + (size_t)bx * 256 + n_off + j * 16;
            wmma::store_matrix_sync(dst, c[i][j], N, wmma::mem_row_major);
        }
}

// ---------------- batched attention score (fp16 wmma, half output) ---------------
#define LDH 72
#define STG_LD 68
__global__ void __launch_bounds__(256)
k_attn_score(const float* __restrict__ Q, const float* __restrict__ Bm,
             const float* __restrict__ bias, __half* __restrict__ Out,
             int jStride, int bOffB, int mode) {
    int i0 = blockIdx.y * 64, j0 = blockIdx.x * 64;
    if (mode == 0) { if (j0 >= i0 + MLEN + 64) return; }
    else           { if (i0 + j0 < 384) return; }

    int g = blockIdx.z;
    int b = g >> 4, h = g & 15;
    const float* Ab = Q + (size_t)b * HD + (size_t)h * DH;
    const float* Bb = Bm + (size_t)b * bOffB + (size_t)h * DH;
    const float* bs = bias + (size_t)h * DH;

    __shared__ __align__(16) char sbuf[2 * 64 * LDH * 2];   // 18,432 B
    __half (*As)[LDH] = (__half(*)[LDH])sbuf;               // [d][i]
    __half (*Bs)[LDH] = (__half(*)[LDH])(sbuf + 64 * LDH * 2);
    float* stage = (float*)sbuf;                            // 64 x STG_LD, reused

    int tid = threadIdx.x;
    for (int t = tid; t < 1024; t += 256) {
        int row = t >> 4, c4 = (t & 15) << 2;
        float4 a = *(const float4*)(Ab + (size_t)(i0 + row) * (BSZ * HD) + c4);
        As[c4 + 0][row] = __float2half_rn(a.x + bs[c4 + 0]);
        As[c4 + 1][row] = __float2half_rn(a.y + bs[c4 + 1]);
        As[c4 + 2][row] = __float2half_rn(a.z + bs[c4 + 2]);
        As[c4 + 3][row] = __float2half_rn(a.w + bs[c4 + 3]);
        float4 v = *(const float4*)(Bb + (size_t)(j0 + row) * jStride + c4);
        Bs[c4 + 0][row] = __float2half_rn(v.x);
        Bs[c4 + 1][row] = __float2half_rn(v.y);
        Bs[c4 + 2][row] = __float2half_rn(v.z);
        Bs[c4 + 3][row] = __float2half_rn(v.w);
    }
    __syncthreads();

    int warp = tid >> 5;
    int mr = warp & 3;
    int nc0 = (warp >> 2) * 2;
    HFragC c[2];
    wmma::fill_fragment(c[0], 0.0f);
    wmma::fill_fragment(c[1], 0.0f);
#pragma unroll
    for (int ks = 0; ks < 4; ks++) {
        HFragA a;
        wmma::load_matrix_sync(a, &As[ks * 16][mr * 16], LDH);
#pragma unroll
        for (int t = 0; t < 2; t++) {
            HFragB bf;
            wmma::load_matrix_sync(bf, &Bs[ks * 16][(nc0 + t) * 16], LDH);
            wmma::mma_sync(c[t], a, bf, c[t]);
        }
    }
    __syncthreads();   // done reading As/Bs; reuse as float staging
#pragma unroll
    for (int t = 0; t < 2; t++)
        wmma::store_matrix_sync(stage + (mr * 16) * STG_LD + (nc0 + t) * 16,
                                c[t], STG_LD, wmma::mem_row_major);
    __syncthreads();

    __half* O = Out + (size_t)g * QLEN * KLEN;
    for (int idx = tid; idx < 64 * 32; idx += 256) {
        int row = idx >> 5, c2 = (idx & 31) << 1;
        __half2 hv = __floats2half2_rn(stage[row * STG_LD + c2],
                                       stage[row * STG_LD + c2 + 1]);
        *(__half2*)(O + (size_t)(i0 + row) * KLEN + j0 + c2) = hv;
    }
}

// ---------------- fused rel-shift + mask + softmax (half in/out) -----------------
__global__ void __launch_bounds__(256)
k_softmax(__half* __restrict__ AC, const __half* __restrict__ BD) {
    int g = blockIdx.y, i = blockIdx.x;
    __half* ac = AC + (size_t)g * QLEN * KLEN + (size_t)i * KLEN;
    const __half* bd = BD + (size_t)g * QLEN * KLEN + (size_t)i * KLEN;
    int tid = threadIdx.x;
    __shared__ float red[256];
    float s[4];
#pragma unroll
    for (int u = 0; u < 4; u++) {
        int j = tid + u * 256;
        bool valid = (j <= i + MLEN);
        s[u] = valid ? (__half2float(ac[j]) + __half2float(bd[j + (QLEN - 1) - i])) * ATT_SCALE
                     : NEGV;
    }
    float m = fmaxf(fmaxf(s[0], s[1]), fmaxf(s[2], s[3]));
    red[tid] = m;
    __syncthreads();
    for (int o = 128; o > 0; o >>= 1) {
        if (tid < o) red[tid] = fmaxf(red[tid], red[tid + o]);
        __syncthreads();
    }
    float M = red[0];
    __syncthreads();
    float e[4], sum = 0.f;
#pragma unroll
    for (int u = 0; u < 4; u++) {
        e[u] = (s[u] > 0.5f * NEGV) ? expf(s[u] - M) : 0.f;
        sum += e[u];
    }
    red[tid] = sum;
    __syncthreads();
    for (int o = 128; o > 0; o >>= 1) {
        if (tid < o) red[tid] += red[tid + o];
        __syncthreads();
    }
    float inv = 1.f / red[0];
#pragma unroll
    for (int u = 0; u < 4; u++) ac[tid + u * 256] = __float2half_rn(e[u] * inv);
}

// ---------------- batched P @ V (fp16 wmma, double-buffered, masked skip) --------
__global__ void __launch_bounds__(256)
k_attn_pv(const __half* __restrict__ P, const float* __restrict__ KV,
          float* __restrict__ vec) {
    int g = blockIdx.y;
    int b = g >> 4, h = g & 15;
    int i0 = blockIdx.x * 64;
    const int kt_end = min(KLEN, i0 + 64 + MLEN);
    const __half* Pb = P + (size_t)g * QLEN * KLEN;
    const float* Vb = KV + (size_t)b * (2 * HD) + HD + (size_t)h * DH;
    __shared__ __half Ps[2][32][LDH];   // [k][i]
    __shared__ __half Vs[2][32][LDH];   // [k][d]
    int tid = threadIdx.x;
    int warp = tid >> 5;
    int mr = warp & 3;
    int nc0 = (warp >> 2) * 2;

    float4 rp;            // 8 halves of P
    float4 rv[2];         // V floats
    auto ldg = [&](int kt) {
        int prow = tid >> 2, pc8 = (tid & 3) << 3;
        rp = *(const float4*)(Pb + (size_t)(i0 + prow) * KLEN + kt + pc8);
#pragma unroll
        for (int it = 0; it < 2; it++) {
            int idx = tid + it * 256;
            int vrow = idx >> 4, vc = (idx & 15) << 2;
            rv[it] = *(const float4*)(Vb + (size_t)(kt + vrow) * (BSZ * 2 * HD) + vc);
        }
    };
    auto sts = [&](int s) {
        int prow = tid >> 2, pc8 = (tid & 3) << 3;
        const __half* hp = (const __half*)&rp;
#pragma unroll
        for (int j = 0; j < 8; j++) Ps[s][pc8 + j][prow] = hp[j];
#pragma unroll
        for (int it = 0; it < 2; it++) {
            int idx = tid + it * 256;
            int vrow = idx >> 4, vc = (idx & 15) << 2;
            *(__half2*)&Vs[s][vrow][vc]     = __floats2half2_rn(rv[it].x, rv[it].y);
            *(__half2*)&Vs[s][vrow][vc + 2] = __floats2half2_rn(rv[it].z, rv[it].w);
        }
    };

    HFragC c[2];
    wmma::fill_fragment(c[0], 0.0f);
    wmma::fill_fragment(c[1], 0.0f);

    ldg(0);
    sts(0);
    __syncthreads();
    int s = 0;
    for (int kt = 0; kt < kt_end; kt += 32) {
        bool nxt = (kt + 32) < kt_end;
        if (nxt) ldg(kt + 32);
#pragma unroll
        for (int ks = 0; ks < 2; ks++) {
            HFragA a;
            wmma::load_matrix_sync(a, &Ps[s][ks * 16][mr * 16], LDH);
#pragma unroll
            for (int t = 0; t < 2; t++) {
                HFragB bf;
                wmma::load_matrix_sync(bf, &Vs[s][ks * 16][(nc0 + t) * 16], LDH);
                wmma::mma_sync(c[t], a, bf, c[t]);
            }
        }
        if (nxt) {
            sts(s ^ 1);
            __syncthreads();
            s ^= 1;
        }
    }
#pragma unroll
    for (int t = 0; t < 2; t++) {
        float* dst = vec + ((size_t)(i0 + mr * 16) * BSZ + b) * HD
                         + (size_t)h * DH + (nc0 + t) * 16;
        wmma::store_matrix_sync(dst, c[t], BSZ * HD, wmma::mem_row_major);
    }
}

// ---------------- layernorm(residual): out = LN(X + R)*g + b ---------------------
__global__ void __launch_bounds__(256)
k_ln(const float* __restrict__ X, const float* __restrict__ R,
     const float* __restrict__ gw, const float* __restrict__ bw,
     float* __restrict__ out) {
    int r = blockIdx.x;
    int tid = threadIdx.x;
    __shared__ float red[256];
    float x[4];
#pragma unroll
    for (int u = 0; u < 4; u++) {
        int d = tid + u * 256;
        x[u] = X[(size_t)r * DM + d] + R[(size_t)r * DM + d];
    }
    float s = x[0] + x[1] + x[2] + x[3];
    red[tid] = s;
    __syncthreads();
    for (int o = 128; o > 0; o >>= 1) {
        if (tid < o) red[tid] += red[tid + o];
        __syncthreads();
    }
    float mu = red[0] * (1.f / DM);
    __syncthreads();
    float v = 0.f;
#pragma unroll
    for (int u = 0; u < 4; u++) { float dd = x[u] - mu; v += dd * dd; }
    red[tid] = v;
    __syncthreads();
    for (int o = 128; o > 0; o >>= 1) {
        if (tid < o) red[tid] += red[tid + o];
        __syncthreads();
    }
    float rstd = rsqrtf(red[0] * (1.f / DM) + 1e-5f);
#pragma unroll
    for (int u = 0; u < 4; u++) {
        int d = tid + u * 256;
        out[(size_t)r * DM + d] = (x[u] - mu) * rstd * gw[d] + bw[d];
    }
}

// ---------------- loss: -(logit[tgt] - logsumexp(row)) ---------------------------
__global__ void __launch_bounds__(256)
k_loss(const float* __restrict__ logits, const int* __restrict__ target,
       float* __restrict__ out) {
    int r = blockIdx.x;
    int tid = threadIdx.x;
    const float* row = logits + (size_t)r * VOCAB;
    float m = -INFINITY, s = 0.f;
    for (int j = tid; j < VOCAB; j += 256) {
        float v = row[j];
        if (v > m) { s = s * expf(m - v) + 1.f; m = v; }
        else s += expf(v - m);
    }
    __shared__ float sm[256], ss[256];
    sm[tid] = m; ss[tid] = s;
    __syncthreads();
    for (int o = 128; o > 0; o >>= 1) {
        if (tid < o) {
            float m1 = sm[tid], m2 = sm[tid + o];
            float M = fmaxf(m1, m2);
            ss[tid] = ss[tid] * expf(m1 - M) + ss[tid + o] * expf(m2 - M);
            sm[tid] = M;
        }
        __syncthreads();
    }
    if (tid == 0) {
        int tgt = target[r];
        out[r] = sm[0] + logf(ss[0]) - row[tgt];
    }
}

// ---------------- host orchestration ---------------------------------------------

static float* sym(const void* s) {
    void* p = nullptr;
    cudaGetSymbolAddress(&p, s);
    return (float*)p;
}

extern "C" void kernel_launch(void* const* d_in, const int* in_sizes, int n_in,
                              void* d_out, int out_size) {
    const int*   data   = (const int*)  d_in[0];
    const int*   target = (const int*)  d_in[1];
    const float* memory = (const float*)d_in[2];
    const float* embW   = (const float*)d_in[3];
    const float* rwb    = (const float*)d_in[4];
    const float* rrb    = (const float*)d_in[5];
    const float* Wq     = (const float*)d_in[6];
    const float* Wkv    = (const float*)d_in[7];
    const float* Wr     = (const float*)d_in[8];
    const float* Wo     = (const float*)d_in[9];
    const float* W1     = (const float*)d_in[10];
    const float* b1     = (const float*)d_in[11];
    const float* W2     = (const float*)d_in[12];
    const float* b2     = (const float*)d_in[13];
    const float* ln1g   = (const float*)d_in[14];
    const float* ln1b   = (const float*)d_in[15];
    const float* ln2g   = (const float*)d_in[16];
    const float* ln2b   = (const float*)d_in[17];

    float* out = (float*)d_out;
    float* loss_out = out;
    float* mems_out = out + (size_t)QLEN * BSZ;

    float*  big  = sym(g_big);
    __half* ac_h = (__half*)big;                 // SCORE_ELEMS halves
    __half* bd_h = ac_h + SCORE_ELEMS;           // SCORE_ELEMS halves
    float*  lg   = big;                          // logits reuse (scores dead by then)
    float* core = sym(g_core);
    float* xmem = sym(g_xmem);
    float* pos  = sym(g_pos);
    float* qb   = sym(g_q);
    float* kvb  = sym(g_kv);
    float* rkb  = sym(g_rk);
    float* vec  = sym(g_vec);
    float* ffb  = sym(g_ff);
    float* tmp  = sym(g_tmp);

    cudaFuncSetAttribute(k_wgemm<0>, cudaFuncAttributeMaxDynamicSharedMemorySize, WG_SMEM);
    cudaFuncSetAttribute(k_wgemm<1>, cudaFuncAttributeMaxDynamicSharedMemorySize, WG_SMEM);

    const size_t layerF = (size_t)QLEN * BSZ * DM;
    const int copy4 = (int)(layerF / 4);

    const size_t outN = (size_t)out_size;
    const size_t lossN = (size_t)QLEN * BSZ;

    k_embed<<<NROW, 256>>>(data, embW, core);
    k_pos<<<dim3(KLEN, 4), 256>>>(pos);
    if (lossN + layerF <= outN)
        k_copy4<<<copy4 / 256, 256>>>((const float4*)core, (float4*)mems_out, copy4);

    for (int l = 0; l < NLAYER; l++) {
        k_copy4<<<copy4 / 256, 256>>>((const float4*)(memory + (size_t)l * layerF),
                                      (float4*)xmem, copy4);
        k_copy4<<<copy4 / 256, 256>>>((const float4*)core, (float4*)(xmem + layerF), copy4);

        k_wgemm<0><<<dim3(HD / 256, NROW / 128), 256, WG_SMEM>>>(
            core, Wq + (size_t)l * DM * HD, nullptr, qb, NROW, HD, DM, 0);
        k_wgemm<0><<<dim3(2 * HD / 256, KROW / 128), 256, WG_SMEM>>>(
            xmem, Wkv + (size_t)l * DM * 2 * HD, nullptr, kvb, KROW, 2 * HD, DM, 0);
        k_wgemm<0><<<dim3(HD / 256, KLEN / 128), 256, WG_SMEM>>>(
            pos, Wr + (size_t)l * DM * HD, nullptr, rkb, KLEN, HD, DM, 0);

        k_attn_score<<<dim3(KLEN / 64, QLEN / 64, BSZ * NH), 256>>>(
            qb, kvb, rwb, ac_h, BSZ * 2 * HD, 2 * HD, 0);
        k_attn_score<<<dim3(KLEN / 64, QLEN / 64, BSZ * NH), 256>>>(
            qb, rkb, rrb, bd_h, HD, 0, 1);

        k_softmax<<<dim3(QLEN, BSZ * NH), 256>>>(ac_h, bd_h);
        k_attn_pv<<<dim3(QLEN / 64, BSZ * NH), 256>>>(ac_h, kvb, vec);

        k_wgemm<0><<<dim3(DM / 256, NROW / 128), 256, WG_SMEM>>>(
            vec, Wo + (size_t)l * HD * DM, nullptr, tmp, NROW, DM, HD, 0);
        k_ln<<<NROW, 256>>>(core, tmp, ln1g + (size_t)l * DM, ln1b + (size_t)l * DM, core);

        k_wgemm<0><<<dim3(DI / 256, NROW / 128), 256, WG_SMEM>>>(
            core, W1 + (size_t)l * DM * DI, b1 + (size_t)l * DI, ffb, NROW, DI, DM, 1);
        k_wgemm<0><<<dim3(DM / 256, NROW / 128), 256, WG_SMEM>>>(
            ffb, W2 + (size_t)l * DI * DM, b2 + (size_t)l * DM, tmp, NROW, DM, DI, 0);
        k_ln<<<NROW, 256>>>(core, tmp, ln2g + (size_t)l * DM, ln2b + (size_t)l * DM, core);

        if (l < NLAYER - 1 && lossN + (size_t)(l + 2) * layerF <= outN)
            k_copy4<<<copy4 / 256, 256>>>((const float4*)core,
                                          (float4*)(mems_out + (size_t)(l + 1) * layerF), copy4);
    }

    k_wgemm<1><<<dim3(VOCAB / 256, NROW / 128), 256, WG_SMEM>>>(
        core, embW, nullptr, lg, NROW, VOCAB, DM, 0);
    k_loss<<<NROW, 256>>>(lg, target, loss_out);
}

// round 14
// speedup vs baseline: 2.4481x; 1.1648x over previous
#include <cuda_runtime.h>
#include <cuda_fp16.h>
#include <math.h>
#include <stdint.h>
#include <mma.h>

using namespace nvcuda;

#define QLEN 512
#define MLEN 512
#define KLEN 1024
#define BSZ 8
#define NH 16
#define DH 64
#define DM 1024
#define HD 1024
#define DI 4096
#define NLAYER 6
#define VOCAB 32000
#define ATT_SCALE 0.125f
#define NEGV -1e30f

#define NROW (QLEN*BSZ)        // 4096
#define KROW (KLEN*BSZ)        // 8192

// ---------------- scratch -------------------------------------------------------
#define SCORE_ELEMS ((size_t)BSZ*NH*QLEN*KLEN)
#define LOGIT_ELEMS ((size_t)NROW*VOCAB)
#define BIG_ELEMS   (2*SCORE_ELEMS)
static_assert(BIG_ELEMS >= LOGIT_ELEMS, "g_big must also fit logits");
__device__ float  g_big [BIG_ELEMS];          // half scores during layers; fp32 logits after
__device__ float  g_core[(size_t)NROW*DM];
__device__ float  g_tmp [(size_t)NROW*DM];
// fp16 world
__device__ __half h_core[(size_t)NROW*DM];
__device__ __half h_xmem[(size_t)KROW*DM];
__device__ __half h_pos [(size_t)KLEN*DM];
__device__ __half h_q   [(size_t)NROW*HD];
__device__ __half h_kv  [(size_t)KROW*2*HD];
__device__ __half h_rk  [(size_t)KLEN*HD];
__device__ __half h_vec [(size_t)NROW*HD];
__device__ __half h_ff  [(size_t)NROW*DI];
__device__ __half h_wq [(size_t)NLAYER*DM*HD];
__device__ __half h_wkv[(size_t)NLAYER*DM*2*HD];
__device__ __half h_wr [(size_t)NLAYER*DM*HD];
__device__ __half h_wo [(size_t)NLAYER*HD*DM];
__device__ __half h_w1 [(size_t)NLAYER*DM*DI];
__device__ __half h_w2 [(size_t)NLAYER*DI*DM];
__device__ __half h_emb[(size_t)VOCAB*DM];

typedef wmma::fragment<wmma::matrix_a, 16, 16, 16, __half, wmma::row_major> HFragAR;
typedef wmma::fragment<wmma::matrix_a, 16, 16, 16, __half, wmma::col_major> HFragA;
typedef wmma::fragment<wmma::matrix_b, 16, 16, 16, __half, wmma::row_major> HFragB;
typedef wmma::fragment<wmma::matrix_b, 16, 16, 16, __half, wmma::col_major> HFragBC;
typedef wmma::fragment<wmma::accumulator, 16, 16, 16, float> HFragC;

// ---------------- conversion / copy utilities -----------------------------------

__global__ void k_f2h(const float* __restrict__ src, __half* __restrict__ dst, int n8) {
    int i = blockIdx.x * blockDim.x + threadIdx.x;
    if (i >= n8) return;
    float4 a = ((const float4*)src)[2 * i];
    float4 b = ((const float4*)src)[2 * i + 1];
    __half2 h[4] = { __floats2half2_rn(a.x, a.y), __floats2half2_rn(a.z, a.w),
                     __floats2half2_rn(b.x, b.y), __floats2half2_rn(b.z, b.w) };
    ((uint4*)dst)[i] = *(uint4*)h;
}

__global__ void k_copyh(const uint4* __restrict__ src, uint4* __restrict__ dst, int n8) {
    int i = blockIdx.x * blockDim.x + threadIdx.x;
    if (i < n8) dst[i] = src[i];
}

__global__ void k_copy4(const float4* __restrict__ src, float4* __restrict__ dst, int n4) {
    int i = blockIdx.x * blockDim.x + threadIdx.x;
    if (i < n4) dst[i] = src[i];
}

__global__ void k_embed(const int* __restrict__ data, const float* __restrict__ embW,
                        float* __restrict__ core, __half* __restrict__ coreh) {
    int r = blockIdx.x;
    int tok = data[r];
    float4 v = ((const float4*)(embW + (size_t)tok * DM))[threadIdx.x];
    ((float4*)(core + (size_t)r * DM))[threadIdx.x] = v;
    __half2 h2[2] = { __floats2half2_rn(v.x, v.y), __floats2half2_rn(v.z, v.w) };
    ((uint2*)(coreh + (size_t)r * DM))[threadIdx.x] = *(uint2*)h2;
}

__global__ void k_pos(__half* __restrict__ pos) {
    int p = blockIdx.x;
    int d = blockIdx.y * 256 + threadIdx.x;
    float ps = (float)(KLEN - 1 - p);
    int idx = (d < DM/2) ? d : (d - DM/2);
    float e = (float)(2 * idx) / (float)DM;
    float inv = powf(10000.0f, -e);
    float v = ps * inv;
    pos[(size_t)p * DM + d] = __float2half_rn((d < DM/2) ? sinf(v) : cosf(v));
}

// ---------------- fp16 GEMM, all-half operands, 128x256 tile, BK=16 --------------
// C = A[M,K] @ B (+bias fp32)(+relu).  BNK0: B [K][N]; BNK1: B [N][K]. OUTH: half C.
#define LDTA 24                       // halves; [m][k] A smem stride
#define LDNB 264                      // halves; [k][n] B mode0 stride
#define A_ST (128 * LDTA)             // 3072 halves
#define B_ST (256 * 24)               // 6144 halves (covers both modes)
#define WG_SMEM ((2*A_ST + 2*B_ST) * 2 + 16 * LDNB * 4)   // 53,760 B

template<int BNK, int OUTH>
__global__ void __launch_bounds__(256, 1)
k_wgemm(const __half* __restrict__ A, const __half* __restrict__ B,
        const float* __restrict__ bias, void* __restrict__ Cv,
        int M, int N, int K, int relu) {
    extern __shared__ char dsmc[];
    __half* As0   = (__half*)dsmc;                          // 2 stages
    __half* Bs0   = (__half*)dsmc + 2 * A_ST;
    float*  biasf = (float*)(dsmc + (2 * A_ST + 2 * B_ST) * 2);

    int tid = threadIdx.x;
    int bx = blockIdx.x, by = blockIdx.y;
    int warp = tid >> 5, lane = tid & 31;
    int m_off = (warp >> 2) * 64;
    int n_off = (warp & 3) * 64;

    const __half* Abase = A + (size_t)by * 128 * K;

    uint4 ra, rb[2];
    auto ldg = [&](int k0) {
        int arow = tid >> 1, ak8 = (tid & 1) << 3;
        ra = *(const uint4*)(Abase + (size_t)arow * K + k0 + ak8);
#pragma unroll
        for (int it = 0; it < 2; it++) {
            int c = tid + it * 256;
            if (BNK == 0) {
                int row = c >> 5, n8 = (c & 31) << 3;
                rb[it] = *(const uint4*)(B + (size_t)(k0 + row) * N + (size_t)bx * 256 + n8);
            } else {
                int row = c >> 1, k8 = (c & 1) << 3;
                rb[it] = *(const uint4*)(B + (size_t)(bx * 256 + row) * K + k0 + k8);
            }
        }
    };
    auto sts = [&](int s) {
        __half* As = As0 + s * A_ST;
        __half* Bs = Bs0 + s * B_ST;
        int arow = tid >> 1, ak8 = (tid & 1) << 3;
        *(uint4*)(As + arow * LDTA + ak8) = ra;
#pragma unroll
        for (int it = 0; it < 2; it++) {
            int c = tid + it * 256;
            if (BNK == 0) {
                int row = c >> 5, n8 = (c & 31) << 3;
                *(uint4*)(Bs + row * LDNB + n8) = rb[it];
            } else {
                int row = c >> 1, k8 = (c & 1) << 3;
                *(uint4*)(Bs + row * 24 + k8) = rb[it];
            }
        }
    };

    if (bias) {
        for (int idx = tid; idx < 16 * 256; idx += 256) {
            int r = idx >> 8, n = idx & 255;
            biasf[r * LDNB + n] = bias[(size_t)bx * 256 + n];
        }
    }

    ldg(0);
    sts(0);
    __syncthreads();

    HFragC c[4][4];
#pragma unroll
    for (int i = 0; i < 4; i++)
#pragma unroll
        for (int j = 0; j < 4; j++) {
            if (bias) wmma::load_matrix_sync(c[i][j], biasf + n_off + j * 16, LDNB,
                                             wmma::mem_row_major);
            else      wmma::fill_fragment(c[i][j], 0.0f);
        }

    int s = 0;
    for (int k0 = 0; k0 < K; k0 += 16) {
        bool nxt = (k0 + 16) < K;
        if (nxt) ldg(k0 + 16);

        const __half* As = As0 + s * A_ST;
        const __half* Bs = Bs0 + s * B_ST;
        HFragAR a[4];
#pragma unroll
        for (int i = 0; i < 4; i++)
            wmma::load_matrix_sync(a[i], As + (m_off + i * 16) * LDTA, LDTA);
        if (BNK == 0) {
            HFragB b[4];
#pragma unroll
            for (int j = 0; j < 4; j++)
                wmma::load_matrix_sync(b[j], Bs + n_off + j * 16, LDNB);
#pragma unroll
            for (int i = 0; i < 4; i++)
#pragma unroll
                for (int j = 0; j < 4; j++)
                    wmma::mma_sync(c[i][j], a[i], b[j], c[i][j]);
        } else {
            HFragBC b[4];
#pragma unroll
            for (int j = 0; j < 4; j++)
                wmma::load_matrix_sync(b[j], Bs + (n_off + j * 16) * 24, 24);
#pragma unroll
            for (int i = 0; i < 4; i++)
#pragma unroll
                for (int j = 0; j < 4; j++)
                    wmma::mma_sync(c[i][j], a[i], b[j], c[i][j]);
        }

        if (nxt) {
            sts(s ^ 1);
            __syncthreads();
            s ^= 1;
        }
    }

    if (relu) {
#pragma unroll
        for (int i = 0; i < 4; i++)
#pragma unroll
            for (int j = 0; j < 4; j++)
#pragma unroll
                for (int e = 0; e < c[i][j].num_elements; e++)
                    c[i][j].x[e] = fmaxf(c[i][j].x[e], 0.0f);
    }

    if (OUTH == 0) {
        float* C = (float*)Cv;
#pragma unroll
        for (int i = 0; i < 4; i++)
#pragma unroll
            for (int j = 0; j < 4; j++)
                wmma::store_matrix_sync(C + (size_t)(by * 128 + m_off + i * 16) * N
                                          + (size_t)bx * 256 + n_off + j * 16,
                                        c[i][j], N, wmma::mem_row_major);
    } else {
        __half* C = (__half*)Cv;
        __syncthreads();                 // smem pipeline done; reuse as staging
        float* stg = (float*)dsmc + warp * 16 * 68;   // 8 warps x 4352 B = 34,816 B
#pragma unroll
        for (int i = 0; i < 4; i++) {
#pragma unroll
            for (int j = 0; j < 4; j++)
                wmma::store_matrix_sync(stg + j * 16, c[i][j], 68, wmma::mem_row_major);
            __syncwarp();
            for (int idx = lane; idx < 16 * 32; idx += 32) {
                int row = idx >> 5, c2 = (idx & 31) << 1;
                __half2 hv = __floats2half2_rn(stg[row * 68 + c2], stg[row * 68 + c2 + 1]);
                *(__half2*)(C + (size_t)(by * 128 + m_off + i * 16 + row) * N
                              + (size_t)bx * 256 + n_off + c2) = hv;
            }
            __syncwarp();
        }
    }
}

// ---------------- attention score (all-half in, half out) ------------------------
#define LDH 72
#define STG_LD 68
__global__ void __launch_bounds__(256)
k_attn_score(const __half* __restrict__ Q, const __half* __restrict__ Bm,
             const float* __restrict__ bias, __half* __restrict__ Out,
             int jStride, int bOffB, int mode) {
    int i0 = blockIdx.y * 64, j0 = blockIdx.x * 64;
    if (mode == 0) { if (j0 >= i0 + MLEN + 64) return; }
    else           { if (i0 + j0 < 384) return; }

    int g = blockIdx.z;
    int b = g >> 4, h = g & 15;
    const __half* Ab = Q + (size_t)b * HD + (size_t)h * DH;
    const __half* Bb = Bm + (size_t)b * bOffB + (size_t)h * DH;
    const float* bs = bias + (size_t)h * DH;

    __shared__ __align__(16) char sbuf[2 * 64 * LDH * 2];
    __half (*As)[LDH] = (__half(*)[LDH])sbuf;
    __half (*Bs)[LDH] = (__half(*)[LDH])(sbuf + 64 * LDH * 2);
    float* stage = (float*)sbuf;

    int tid = threadIdx.x;
    for (int t = tid; t < 1024; t += 256) {
        int row = t >> 4, c4 = (t & 15) << 2;
        const __half* qa = Ab + (size_t)(i0 + row) * (BSZ * HD) + c4;
#pragma unroll
        for (int u = 0; u < 4; u++)
            As[c4 + u][row] = __float2half_rn(__half2float(qa[u]) + bs[c4 + u]);
        const __half* kb = Bb + (size_t)(j0 + row) * jStride + c4;
#pragma unroll
        for (int u = 0; u < 4; u++)
            Bs[c4 + u][row] = kb[u];
    }
    __syncthreads();

    int warp = tid >> 5;
    int mr = warp & 3;
    int nc0 = (warp >> 2) * 2;
    HFragC c[2];
    wmma::fill_fragment(c[0], 0.0f);
    wmma::fill_fragment(c[1], 0.0f);
#pragma unroll
    for (int ks = 0; ks < 4; ks++) {
        HFragA a;
        wmma::load_matrix_sync(a, &As[ks * 16][mr * 16], LDH);
#pragma unroll
        for (int t = 0; t < 2; t++) {
            HFragB bf;
            wmma::load_matrix_sync(bf, &Bs[ks * 16][(nc0 + t) * 16], LDH);
            wmma::mma_sync(c[t], a, bf, c[t]);
        }
    }
    __syncthreads();
#pragma unroll
    for (int t = 0; t < 2; t++)
        wmma::store_matrix_sync(stage + (mr * 16) * STG_LD + (nc0 + t) * 16,
                                c[t], STG_LD, wmma::mem_row_major);
    __syncthreads();

    __half* O = Out + (size_t)g * QLEN * KLEN;
    for (int idx = tid; idx < 64 * 32; idx += 256) {
        int row = idx >> 5, c2 = (idx & 31) << 1;
        __half2 hv = __floats2half2_rn(stage[row * STG_LD + c2],
                                       stage[row * STG_LD + c2 + 1]);
        *(__half2*)(O + (size_t)(i0 + row) * KLEN + j0 + c2) = hv;
    }
}

// ---------------- rel-shift + mask + softmax (half) ------------------------------
__global__ void __launch_bounds__(256)
k_softmax(__half* __restrict__ AC, const __half* __restrict__ BD) {
    int g = blockIdx.y, i = blockIdx.x;
    __half* ac = AC + (size_t)g * QLEN * KLEN + (size_t)i * KLEN;
    const __half* bd = BD + (size_t)g * QLEN * KLEN + (size_t)i * KLEN;
    int tid = threadIdx.x;
    __shared__ float red[256];
    float s[4];
#pragma unroll
    for (int u = 0; u < 4; u++) {
        int j = tid + u * 256;
        bool valid = (j <= i + MLEN);
        s[u] = valid ? (__half2float(ac[j]) + __half2float(bd[j + (QLEN - 1) - i])) * ATT_SCALE
                     : NEGV;
    }
    float m = fmaxf(fmaxf(s[0], s[1]), fmaxf(s[2], s[3]));
    red[tid] = m;
    __syncthreads();
    for (int o = 128; o > 0; o >>= 1) {
        if (tid < o) red[tid] = fmaxf(red[tid], red[tid + o]);
        __syncthreads();
    }
    float M = red[0];
    __syncthreads();
    float e[4], sum = 0.f;
#pragma unroll
    for (int u = 0; u < 4; u++) {
        e[u] = (s[u] > 0.5f * NEGV) ? expf(s[u] - M) : 0.f;
        sum += e[u];
    }
    red[tid] = sum;
    __syncthreads();
    for (int o = 128; o > 0; o >>= 1) {
        if (tid < o) red[tid] += red[tid + o];
        __syncthreads();
    }
    float inv = 1.f / red[0];
#pragma unroll
    for (int u = 0; u < 4; u++) ac[tid + u * 256] = __float2half_rn(e[u] * inv);
}

// ---------------- P @ V (all-half, half out, masked skip) ------------------------
__global__ void __launch_bounds__(256)
k_attn_pv(const __half* __restrict__ P, const __half* __restrict__ KV,
          __half* __restrict__ vec) {
    int g = blockIdx.y;
    int b = g >> 4, h = g & 15;
    int i0 = blockIdx.x * 64;
    const int kt_end = min(KLEN, i0 + 64 + MLEN);
    const __half* Pb = P + (size_t)g * QLEN * KLEN;
    const __half* Vb = KV + (size_t)b * (2 * HD) + HD + (size_t)h * DH;
    __shared__ __half Ps[2][32][LDH];
    __shared__ __half Vs[2][32][LDH];
    __shared__ float pvstg[8][16][36];
    int tid = threadIdx.x;
    int warp = tid >> 5, lane = tid & 31;
    int mr = warp & 3;
    int nc0 = (warp >> 2) * 2;

    uint4 rp, rv;
    auto ldg = [&](int kt) {
        int prow = tid >> 2, pc8 = (tid & 3) << 3;
        rp = *(const uint4*)(Pb + (size_t)(i0 + prow) * KLEN + kt + pc8);
        int vrow = tid >> 3, vc8 = (tid & 7) << 3;
        rv = *(const uint4*)(Vb + (size_t)(kt + vrow) * (BSZ * 2 * HD) + vc8);
    };
    auto sts = [&](int s) {
        int prow = tid >> 2, pc8 = (tid & 3) << 3;
        const __half* hp = (const __half*)&rp;
#pragma unroll
        for (int j = 0; j < 8; j++) Ps[s][pc8 + j][prow] = hp[j];
        int vrow = tid >> 3, vc8 = (tid & 7) << 3;
        *(uint4*)&Vs[s][vrow][vc8] = rv;
    };

    HFragC c[2];
    wmma::fill_fragment(c[0], 0.0f);
    wmma::fill_fragment(c[1], 0.0f);

    ldg(0);
    sts(0);
    __syncthreads();
    int s = 0;
    for (int kt = 0; kt < kt_end; kt += 32) {
        bool nxt = (kt + 32) < kt_end;
        if (nxt) ldg(kt + 32);
#pragma unroll
        for (int ks = 0; ks < 2; ks++) {
            HFragA a;
            wmma::load_matrix_sync(a, &Ps[s][ks * 16][mr * 16], LDH);
#pragma unroll
            for (int t = 0; t < 2; t++) {
                HFragB bf;
                wmma::load_matrix_sync(bf, &Vs[s][ks * 16][(nc0 + t) * 16], LDH);
                wmma::mma_sync(c[t], a, bf, c[t]);
            }
        }
        if (nxt) {
            sts(s ^ 1);
            __syncthreads();
            s ^= 1;
        }
    }
#pragma unroll
    for (int t = 0; t < 2; t++)
        wmma::store_matrix_sync(&pvstg[warp][0][t * 16], c[t], 36, wmma::mem_row_major);
    __syncwarp();
    for (int idx = lane; idx < 16 * 16; idx += 32) {
        int row = idx >> 4, c2 = (idx & 15) << 1;
        __half2 hv = __floats2half2_rn(pvstg[warp][row][c2], pvstg[warp][row][c2 + 1]);
        *(__half2*)(vec + ((size_t)(i0 + mr * 16 + row) * BSZ + b) * HD
                        + (size_t)h * DH + nc0 * 16 + c2) = hv;
    }
}

// ---------------- layernorm(residual): fp32 out + fp16 out -----------------------
__global__ void __launch_bounds__(256)
k_ln(const float* __restrict__ X, const float* __restrict__ R,
     const float* __restrict__ gw, const float* __restrict__ bw,
     float* __restrict__ out, __half* __restrict__ outh) {
    int r = blockIdx.x;
    int tid = threadIdx.x;
    __shared__ float red[256];
    float x[4];
#pragma unroll
    for (int u = 0; u < 4; u++) {
        int d = tid + u * 256;
        x[u] = X[(size_t)r * DM + d] + R[(size_t)r * DM + d];
    }
    float s = x[0] + x[1] + x[2] + x[3];
    red[tid] = s;
    __syncthreads();
    for (int o = 128; o > 0; o >>= 1) {
        if (tid < o) red[tid] += red[tid + o];
        __syncthreads();
    }
    float mu = red[0] * (1.f / DM);
    __syncthreads();
    float v = 0.f;
#pragma unroll
    for (int u = 0; u < 4; u++) { float dd = x[u] - mu; v += dd * dd; }
    red[tid] = v;
    __syncthreads();
    for (int o = 128; o > 0; o >>= 1) {
        if (tid < o) red[tid] += red[tid + o];
        __syncthreads();
    }
    float rstd = rsqrtf(red[0] * (1.f / DM) + 1e-5f);
#pragma unroll
    for (int u = 0; u < 4; u++) {
        int d = tid + u * 256;
        float y = (x[u] - mu) * rstd * gw[d] + bw[d];
        out[(size_t)r * DM + d] = y;
        outh[(size_t)r * DM + d] = __float2half_rn(y);
    }
}

// ---------------- loss ------------------------------------------------------------
__global__ void __launch_bounds__(256)
k_loss(const float* __restrict__ logits, const int* __restrict__ target,
       float* __restrict__ out) {
    int r = blockIdx.x;
    int tid = threadIdx.x;
    const float* row = logits + (size_t)r * VOCAB;
    float m = -INFINITY, s = 0.f;
    for (int j = tid; j < VOCAB; j += 256) {
        float v = row[j];
        if (v > m) { s = s * expf(m - v) + 1.f; m = v; }
        else s += expf(v - m);
    }
    __shared__ float sm[256], ss[256];
    sm[tid] = m; ss[tid] = s;
    __syncthreads();
    for (int o = 128; o > 0; o >>= 1) {
        if (tid < o) {
            float m1 = sm[tid], m2 = sm[tid + o];
            float M = fmaxf(m1, m2);
            ss[tid] = ss[tid] * expf(m1 - M) + ss[tid + o] * expf(m2 - M);
            sm[tid] = M;
        }
        __syncthreads();
    }
    if (tid == 0) {
        int tgt = target[r];
        out[r] = sm[0] + logf(ss[0]) - row[tgt];
    }
}

// ---------------- host orchestration ---------------------------------------------

static void* sym(const void* s) {
    void* p = nullptr;
    cudaGetSymbolAddress(&p, s);
    return p;
}

extern "C" void kernel_launch(void* const* d_in, const int* in_sizes, int n_in,
                              void* d_out, int out_size) {
    const int*   data   = (const int*)  d_in[0];
    const int*   target = (const int*)  d_in[1];
    const float* memory = (const float*)d_in[2];
    const float* embW   = (const float*)d_in[3];
    const float* rwb    = (const float*)d_in[4];
    const float* rrb    = (const float*)d_in[5];
    const float* Wq     = (const float*)d_in[6];
    const float* Wkv    = (const float*)d_in[7];
    const float* Wr     = (const float*)d_in[8];
    const float* Wo     = (const float*)d_in[9];
    const float* W1     = (const float*)d_in[10];
    const float* b1     = (const float*)d_in[11];
    const float* W2     = (const float*)d_in[12];
    const float* b2     = (const float*)d_in[13];
    const float* ln1g   = (const float*)d_in[14];
    const float* ln1b   = (const float*)d_in[15];
    const float* ln2g   = (const float*)d_in[16];
    const float* ln2b   = (const float*)d_in[17];

    float* out = (float*)d_out;
    float* loss_out = out;
    float* mems_out = out + (size_t)QLEN * BSZ;

    float*  big   = (float*)sym(g_big);
    __half* ac_h  = (__half*)big;
    __half* bd_h  = ac_h + SCORE_ELEMS;
    float*  lg    = big;
    float*  core  = (float*)sym(g_core);
    float*  tmp   = (float*)sym(g_tmp);
    __half* coreh = (__half*)sym(h_core);
    __half* xmemh = (__half*)sym(h_xmem);
    __half* posh  = (__half*)sym(h_pos);
    __half* qh    = (__half*)sym(h_q);
    __half* kvh   = (__half*)sym(h_kv);
    __half* rkh   = (__half*)sym(h_rk);
    __half* vech  = (__half*)sym(h_vec);
    __half* ffh   = (__half*)sym(h_ff);
    __half* wqh   = (__half*)sym(h_wq);
    __half* wkvh  = (__half*)sym(h_wkv);
    __half* wrh   = (__half*)sym(h_wr);
    __half* woh   = (__half*)sym(h_wo);
    __half* w1h   = (__half*)sym(h_w1);
    __half* w2h   = (__half*)sym(h_w2);
    __half* embh  = (__half*)sym(h_emb);

    cudaFuncSetAttribute(k_wgemm<0,0>, cudaFuncAttributeMaxDynamicSharedMemorySize, WG_SMEM);
    cudaFuncSetAttribute(k_wgemm<0,1>, cudaFuncAttributeMaxDynamicSharedMemorySize, WG_SMEM);
    cudaFuncSetAttribute(k_wgemm<1,0>, cudaFuncAttributeMaxDynamicSharedMemorySize, WG_SMEM);

    const size_t layerF = (size_t)QLEN * BSZ * DM;
    const int copy4 = (int)(layerF / 4);
    const int copy8 = (int)(layerF / 8);

    const size_t outN = (size_t)out_size;
    const size_t lossN = (size_t)QLEN * BSZ;

    auto cvt = [&](const float* s, __half* d, size_t n) {
        int n8 = (int)(n / 8);
        k_f2h<<<(n8 + 255) / 256, 256>>>(s, d, n8);
    };

    // one-time (per replay) weight conversions
    cvt(Wq,  wqh,  (size_t)NLAYER * DM * HD);
    cvt(Wkv, wkvh, (size_t)NLAYER * DM * 2 * HD);
    cvt(Wr,  wrh,  (size_t)NLAYER * DM * HD);
    cvt(Wo,  woh,  (size_t)NLAYER * HD * DM);
    cvt(W1,  w1h,  (size_t)NLAYER * DM * DI);
    cvt(W2,  w2h,  (size_t)NLAYER * DI * DM);
    cvt(embW, embh, (size_t)VOCAB * DM);

    k_embed<<<NROW, 256>>>(data, embW, core, coreh);
    k_pos<<<dim3(KLEN, 4), 256>>>(posh);
    if (lossN + layerF <= outN)
        k_copy4<<<copy4 / 256, 256>>>((const float4*)core, (float4*)mems_out, copy4);

    for (int l = 0; l < NLAYER; l++) {
        cvt(memory + (size_t)l * layerF, xmemh, layerF);
        k_copyh<<<copy8 / 256, 256>>>((const uint4*)coreh, (uint4*)(xmemh + layerF), copy8);

        k_wgemm<0,1><<<dim3(HD / 256, NROW / 128), 256, WG_SMEM>>>(
            coreh, wqh + (size_t)l * DM * HD, nullptr, qh, NROW, HD, DM, 0);
        k_wgemm<0,1><<<dim3(2 * HD / 256, KROW / 128), 256, WG_SMEM>>>(
            xmemh, wkvh + (size_t)l * DM * 2 * HD, nullptr, kvh, KROW, 2 * HD, DM, 0);
        k_wgemm<0,1><<<dim3(HD / 256, KLEN / 128), 256, WG_SMEM>>>(
            posh, wrh + (size_t)l * DM * HD, nullptr, rkh, KLEN, HD, DM, 0);

        k_attn_score<<<dim3(KLEN / 64, QLEN / 64, BSZ * NH), 256>>>(
            qh, kvh, rwb, ac_h, BSZ * 2 * HD, 2 * HD, 0);
        k_attn_score<<<dim3(KLEN / 64, QLEN / 64, BSZ * NH), 256>>>(
            qh, rkh, rrb, bd_h, HD, 0, 1);

        k_softmax<<<dim3(QLEN, BSZ * NH), 256>>>(ac_h, bd_h);
        k_attn_pv<<<dim3(QLEN / 64, BSZ * NH), 256>>>(ac_h, kvh, vech);

        k_wgemm<0,0><<<dim3(DM / 256, NROW / 128), 256, WG_SMEM>>>(
            vech, woh + (size_t)l * HD * DM, nullptr, tmp, NROW, DM, HD, 0);
        k_ln<<<NROW, 256>>>(core, tmp, ln1g + (size_t)l * DM, ln1b + (size_t)l * DM,
                            core, coreh);

        k_wgemm<0,1><<<dim3(DI / 256, NROW / 128), 256, WG_SMEM>>>(
            coreh, w1h + (size_t)l * DM * DI, b1 + (size_t)l * DI, ffh, NROW, DI, DM, 1);
        k_wgemm<0,0><<<dim3(DM / 256, NROW / 128), 256, WG_SMEM>>>(
            ffh, w2h + (size_t)l * DI * DM, b2 + (size_t)l * DM, tmp, NROW, DM, DI, 0);
        k_ln<<<NROW, 256>>>(core, tmp, ln2g + (size_t)l * DM, ln2b + (size_t)l * DM,
                            core, coreh);

        if (l < NLAYER - 1 && lossN + (size_t)(l + 2) * layerF <= outN)
            k_copy4<<<copy4 / 256, 256>>>((const float4*)core,
                                          (float4*)(mems_out + (size_t)(l + 1) * layerF), copy4);
    }

    k_wgemm<1,0><<<dim3(VOCAB / 256, NROW / 128), 256, WG_SMEM>>>(
        coreh, embh, nullptr, lg, NROW, VOCAB, DM, 0);
    k_loss<<<NROW, 256>>>(lg, target, loss_out);
}

// round 15
// speedup vs baseline: 2.5029x; 1.0224x over previous
#include <cuda_runtime.h>
#include <cuda_fp16.h>
#include <math.h>
#include <stdint.h>
#include <mma.h>

using namespace nvcuda;

#define QLEN 512
#define MLEN 512
#define KLEN 1024
#define BSZ 8
#define NH 16
#define DH 64
#define DM 1024
#define HD 1024
#define DI 4096
#define NLAYER 6
#define VOCAB 32000
#define ATT_SCALE 0.125f
#define NEGV -1e30f

#define NROW (QLEN*BSZ)        // 4096
#define KROW (KLEN*BSZ)        // 8192
#define NPART 500              // logits partials per row: (VOCAB/256)*4

// ---------------- scratch -------------------------------------------------------
#define SCORE_ELEMS ((size_t)BSZ*NH*QLEN*KLEN)
#define BIG_ELEMS   (2*SCORE_ELEMS)
__device__ float  g_big [BIG_ELEMS];          // half scores live here
__device__ float  g_core[(size_t)NROW*DM];
__device__ float  g_tmp [(size_t)NROW*DM];    // also holds logits partials (4096*500*2 floats)
static_assert((size_t)NROW * NPART * 2 <= (size_t)NROW * DM, "partials fit g_tmp");
// fp16 world
__device__ __half h_core[(size_t)NROW*DM];
__device__ __half h_xmem[(size_t)KROW*DM];
__device__ __half h_pos [(size_t)KLEN*DM];
__device__ __half h_q   [(size_t)NROW*HD];
__device__ __half h_kv  [(size_t)KROW*2*HD];
__device__ __half h_rk  [(size_t)NLAYER*KLEN*HD];
__device__ __half h_vec [(size_t)NROW*HD];
__device__ __half h_ff  [(size_t)NROW*DI];
__device__ __half h_wq [(size_t)NLAYER*DM*HD];
__device__ __half h_wkv[(size_t)NLAYER*DM*2*HD];
__device__ __half h_wr [(size_t)NLAYER*DM*HD];
__device__ __half h_wo [(size_t)NLAYER*HD*DM];
__device__ __half h_w1 [(size_t)NLAYER*DM*DI];
__device__ __half h_w2 [(size_t)NLAYER*DI*DM];
__device__ __half h_emb[(size_t)VOCAB*DM];

typedef wmma::fragment<wmma::matrix_a, 16, 16, 16, __half, wmma::row_major> HFragAR;
typedef wmma::fragment<wmma::matrix_a, 16, 16, 16, __half, wmma::col_major> HFragA;
typedef wmma::fragment<wmma::matrix_b, 16, 16, 16, __half, wmma::row_major> HFragB;
typedef wmma::fragment<wmma::matrix_b, 16, 16, 16, __half, wmma::col_major> HFragBC;
typedef wmma::fragment<wmma::accumulator, 16, 16, 16, float> HFragC;

// ---------------- conversion / copy utilities -----------------------------------

__global__ void k_f2h(const float* __restrict__ src, __half* __restrict__ dst, int n8) {
    int i = blockIdx.x * blockDim.x + threadIdx.x;
    if (i >= n8) return;
    float4 a = ((const float4*)src)[2 * i];
    float4 b = ((const float4*)src)[2 * i + 1];
    __half2 h[4] = { __floats2half2_rn(a.x, a.y), __floats2half2_rn(a.z, a.w),
                     __floats2half2_rn(b.x, b.y), __floats2half2_rn(b.z, b.w) };
    ((uint4*)dst)[i] = *(uint4*)h;
}

__global__ void k_copyh(const uint4* __restrict__ src, uint4* __restrict__ dst, int n8) {
    int i = blockIdx.x * blockDim.x + threadIdx.x;
    if (i < n8) dst[i] = src[i];
}

__global__ void k_copy4(const float4* __restrict__ src, float4* __restrict__ dst, int n4) {
    int i = blockIdx.x * blockDim.x + threadIdx.x;
    if (i < n4) dst[i] = src[i];
}

__global__ void k_embed(const int* __restrict__ data, const float* __restrict__ embW,
                        float* __restrict__ core, __half* __restrict__ coreh) {
    int r = blockIdx.x;
    int tok = data[r];
    float4 v = ((const float4*)(embW + (size_t)tok * DM))[threadIdx.x];
    ((float4*)(core + (size_t)r * DM))[threadIdx.x] = v;
    __half2 h2[2] = { __floats2half2_rn(v.x, v.y), __floats2half2_rn(v.z, v.w) };
    ((uint2*)(coreh + (size_t)r * DM))[threadIdx.x] = *(uint2*)h2;
}

__global__ void k_pos(__half* __restrict__ pos) {
    int p = blockIdx.x;
    int d = blockIdx.y * 256 + threadIdx.x;
    float ps = (float)(KLEN - 1 - p);
    int idx = (d < DM/2) ? d : (d - DM/2);
    float e = (float)(2 * idx) / (float)DM;
    float inv = powf(10000.0f, -e);
    float v = ps * inv;
    pos[(size_t)p * DM + d] = __float2half_rn((d < DM/2) ? sinf(v) : cosf(v));
}

// ---------------- fp16 GEMM, all-half operands, 128x256 tile, BK=16 --------------
// C = A[M,K] @ B (+bias fp32)(+relu). BNK0: B [K][N]; BNK1: B [N][K]. OUTH: half C.
// grid.z batching: B += z*bz, C += z*cz (elements).
#define LDTA 24
#define LDNB 264
#define A_ST (128 * LDTA)
#define B_ST (256 * 24)
#define WG_SMEM ((2*A_ST + 2*B_ST) * 2 + 16 * LDNB * 4)   // 53,760 B

template<int BNK, int OUTH>
__global__ void __launch_bounds__(256, 1)
k_wgemm(const __half* __restrict__ A, const __half* __restrict__ Bg,
        const float* __restrict__ bias, void* __restrict__ Cv,
        int M, int N, int K, int relu, size_t bz, size_t cz) {
    extern __shared__ char dsmc[];
    __half* As0   = (__half*)dsmc;
    __half* Bs0   = (__half*)dsmc + 2 * A_ST;
    float*  biasf = (float*)(dsmc + (2 * A_ST + 2 * B_ST) * 2);

    int tid = threadIdx.x;
    int bx = blockIdx.x, by = blockIdx.y, bzid = blockIdx.z;
    int warp = tid >> 5, lane = tid & 31;
    int m_off = (warp >> 2) * 64;
    int n_off = (warp & 3) * 64;

    const __half* B = Bg + (size_t)bzid * bz;
    const __half* Abase = A + (size_t)by * 128 * K;

    uint4 ra, rb[2];
    auto ldg = [&](int k0) {
        int arow = tid >> 1, ak8 = (tid & 1) << 3;
        ra = *(const uint4*)(Abase + (size_t)arow * K + k0 + ak8);
#pragma unroll
        for (int it = 0; it < 2; it++) {
            int c = tid + it * 256;
            if (BNK == 0) {
                int row = c >> 5, n8 = (c & 31) << 3;
                rb[it] = *(const uint4*)(B + (size_t)(k0 + row) * N + (size_t)bx * 256 + n8);
            } else {
                int row = c >> 1, k8 = (c & 1) << 3;
                rb[it] = *(const uint4*)(B + (size_t)(bx * 256 + row) * K + k0 + k8);
            }
        }
    };
    auto sts = [&](int s) {
        __half* As = As0 + s * A_ST;
        __half* Bs = Bs0 + s * B_ST;
        int arow = tid >> 1, ak8 = (tid & 1) << 3;
        *(uint4*)(As + arow * LDTA + ak8) = ra;
#pragma unroll
        for (int it = 0; it < 2; it++) {
            int c = tid + it * 256;
            if (BNK == 0) {
                int row = c >> 5, n8 = (c & 31) << 3;
                *(uint4*)(Bs + row * LDNB + n8) = rb[it];
            } else {
                int row = c >> 1, k8 = (c & 1) << 3;
                *(uint4*)(Bs + row * 24 + k8) = rb[it];
            }
        }
    };

    if (bias) {
        for (int idx = tid; idx < 16 * 256; idx += 256) {
            int r = idx >> 8, n = idx & 255;
            biasf[r * LDNB + n] = bias[(size_t)bx * 256 + n];
        }
    }

    ldg(0);
    sts(0);
    __syncthreads();

    HFragC c[4][4];
#pragma unroll
    for (int i = 0; i < 4; i++)
#pragma unroll
        for (int j = 0; j < 4; j++) {
            if (bias) wmma::load_matrix_sync(c[i][j], biasf + n_off + j * 16, LDNB,
                                             wmma::mem_row_major);
            else      wmma::fill_fragment(c[i][j], 0.0f);
        }

    int s = 0;
    for (int k0 = 0; k0 < K; k0 += 16) {
        bool nxt = (k0 + 16) < K;
        if (nxt) ldg(k0 + 16);

        const __half* As = As0 + s * A_ST;
        const __half* Bs = Bs0 + s * B_ST;
        HFragAR a[4];
#pragma unroll
        for (int i = 0; i < 4; i++)
            wmma::load_matrix_sync(a[i], As + (m_off + i * 16) * LDTA, LDTA);
        if (BNK == 0) {
            HFragB b[4];
#pragma unroll
            for (int j = 0; j < 4; j++)
                wmma::load_matrix_sync(b[j], Bs + n_off + j * 16, LDNB);
#pragma unroll
            for (int i = 0; i < 4; i++)
#pragma unroll
                for (int j = 0; j < 4; j++)
                    wmma::mma_sync(c[i][j], a[i], b[j], c[i][j]);
        } else {
            HFragBC b[4];
#pragma unroll
            for (int j = 0; j < 4; j++)
                wmma::load_matrix_sync(b[j], Bs + (n_off + j * 16) * 24, 24);
#pragma unroll
            for (int i = 0; i < 4; i++)
#pragma unroll
                for (int j = 0; j < 4; j++)
                    wmma::mma_sync(c[i][j], a[i], b[j], c[i][j]);
        }

        if (nxt) {
            sts(s ^ 1);
            __syncthreads();
            s ^= 1;
        }
    }

    if (relu) {
#pragma unroll
        for (int i = 0; i < 4; i++)
#pragma unroll
            for (int j = 0; j < 4; j++)
#pragma unroll
                for (int e = 0; e < c[i][j].num_elements; e++)
                    c[i][j].x[e] = fmaxf(c[i][j].x[e], 0.0f);
    }

    if (OUTH == 0) {
        float* C = (float*)Cv + (size_t)bzid * cz;
#pragma unroll
        for (int i = 0; i < 4; i++)
#pragma unroll
            for (int j = 0; j < 4; j++)
                wmma::store_matrix_sync(C + (size_t)(by * 128 + m_off + i * 16) * N
                                          + (size_t)bx * 256 + n_off + j * 16,
                                        c[i][j], N, wmma::mem_row_major);
    } else {
        __half* C = (__half*)Cv + (size_t)bzid * cz;
        __syncthreads();
        float* stg = (float*)dsmc + warp * 16 * 68;
#pragma unroll
        for (int i = 0; i < 4; i++) {
#pragma unroll
            for (int j = 0; j < 4; j++)
                wmma::store_matrix_sync(stg + j * 16, c[i][j], 68, wmma::mem_row_major);
            __syncwarp();
            for (int idx = lane; idx < 16 * 32; idx += 32) {
                int row = idx >> 5, c2 = (idx & 31) << 1;
                __half2 hv = __floats2half2_rn(stg[row * 68 + c2], stg[row * 68 + c2 + 1]);
                *(__half2*)(C + (size_t)(by * 128 + m_off + i * 16 + row) * N
                              + (size_t)bx * 256 + n_off + c2) = hv;
            }
            __syncwarp();
        }
    }
}

// ---------------- fused logits GEMM + partial logsumexp --------------------------
// Computes core @ emb^T tile (128x256) and emits per-row (max, sumexp) partials.
__global__ void __launch_bounds__(256, 1)
k_logits(const __half* __restrict__ A, const __half* __restrict__ B,
         float* __restrict__ pm, float* __restrict__ ps, int N, int K) {
    extern __shared__ char dsmc[];
    __half* As0 = (__half*)dsmc;
    __half* Bs0 = (__half*)dsmc + 2 * A_ST;

    int tid = threadIdx.x;
    int bx = blockIdx.x, by = blockIdx.y;
    int warp = tid >> 5, lane = tid & 31;
    int m_off = (warp >> 2) * 64;
    int n_off = (warp & 3) * 64;

    const __half* Abase = A + (size_t)by * 128 * K;

    uint4 ra, rb[2];
    auto ldg = [&](int k0) {
        int arow = tid >> 1, ak8 = (tid & 1) << 3;
        ra = *(const uint4*)(Abase + (size_t)arow * K + k0 + ak8);
#pragma unroll
        for (int it = 0; it < 2; it++) {
            int c = tid + it * 256;
            int row = c >> 1, k8 = (c & 1) << 3;
            rb[it] = *(const uint4*)(B + (size_t)(bx * 256 + row) * K + k0 + k8);
        }
    };
    auto sts = [&](int s) {
        __half* As = As0 + s * A_ST;
        __half* Bs = Bs0 + s * B_ST;
        int arow = tid >> 1, ak8 = (tid & 1) << 3;
        *(uint4*)(As + arow * LDTA + ak8) = ra;
#pragma unroll
        for (int it = 0; it < 2; it++) {
            int c = tid + it * 256;
            int row = c >> 1, k8 = (c & 1) << 3;
            *(uint4*)(Bs + row * 24 + k8) = rb[it];
        }
    };

    ldg(0);
    sts(0);
    __syncthreads();

    HFragC c[4][4];
#pragma unroll
    for (int i = 0; i < 4; i++)
#pragma unroll
        for (int j = 0; j < 4; j++) wmma::fill_fragment(c[i][j], 0.0f);

    int s = 0;
    for (int k0 = 0; k0 < K; k0 += 16) {
        bool nxt = (k0 + 16) < K;
        if (nxt) ldg(k0 + 16);
        const __half* As = As0 + s * A_ST;
        const __half* Bs = Bs0 + s * B_ST;
        HFragAR a[4];
        HFragBC b[4];
#pragma unroll
        for (int i = 0; i < 4; i++)
            wmma::load_matrix_sync(a[i], As + (m_off + i * 16) * LDTA, LDTA);
#pragma unroll
        for (int j = 0; j < 4; j++)
            wmma::load_matrix_sync(b[j], Bs + (n_off + j * 16) * 24, 24);
#pragma unroll
        for (int i = 0; i < 4; i++)
#pragma unroll
            for (int j = 0; j < 4; j++)
                wmma::mma_sync(c[i][j], a[i], b[j], c[i][j]);
        if (nxt) {
            sts(s ^ 1);
            __syncthreads();
            s ^= 1;
        }
    }

    // epilogue: per-row max/sumexp over this warp's 64 columns
    __syncthreads();
    float* stg = (float*)dsmc + warp * 16 * 68;
    int row = lane >> 1, half = lane & 1;
#pragma unroll
    for (int i = 0; i < 4; i++) {
#pragma unroll
        for (int j = 0; j < 4; j++)
            wmma::store_matrix_sync(stg + j * 16, c[i][j], 68, wmma::mem_row_major);
        __syncwarp();
        float m = -INFINITY, sm = 0.f;
#pragma unroll 8
        for (int cc = half * 32; cc < half * 32 + 32; cc++) {
            float v = stg[row * 68 + cc];
            if (v > m) { sm = sm * expf(m - v) + 1.f; m = v; }
            else sm += expf(v - m);
        }
        float mo = __shfl_xor_sync(0xffffffff, m, 1);
        float so = __shfl_xor_sync(0xffffffff, sm, 1);
        float M = fmaxf(m, mo);
        float S = sm * expf(m - M) + so * expf(mo - M);
        if (!half) {
            int gr = by * 128 + m_off + i * 16 + row;
            int pidx = bx * 4 + (warp & 3);
            pm[(size_t)gr * NPART + pidx] = M;
            ps[(size_t)gr * NPART + pidx] = S;
        }
        __syncwarp();
    }
}

// ---------------- final loss: merge partials + target dot ------------------------
__global__ void __launch_bounds__(128)
k_loss_final(const float* __restrict__ pm, const float* __restrict__ ps,
             const __half* __restrict__ coreh, const __half* __restrict__ embh,
             const int* __restrict__ target, float* __restrict__ out) {
    int r = blockIdx.x;
    int tid = threadIdx.x;
    float m = -INFINITY, s = 0.f;
    for (int p = tid; p < NPART; p += 128) {
        float m2 = pm[(size_t)r * NPART + p];
        float s2 = ps[(size_t)r * NPART + p];
        float M = fmaxf(m, m2);
        s = s * expf(m - M) + s2 * expf(m2 - M);
        m = M;
    }
    __shared__ float sm[128], ss[128], sd[128];
    sm[tid] = m; ss[tid] = s;
    __syncthreads();
    for (int o = 64; o > 0; o >>= 1) {
        if (tid < o) {
            float m1 = sm[tid], m2 = sm[tid + o];
            float M = fmaxf(m1, m2);
            ss[tid] = ss[tid] * expf(m1 - M) + ss[tid + o] * expf(m2 - M);
            sm[tid] = M;
        }
        __syncthreads();
    }
    int tgt = target[r];
    float d = 0.f;
    for (int k = tid; k < DM; k += 128)
        d += __half2float(coreh[(size_t)r * DM + k]) * __half2float(embh[(size_t)tgt * DM + k]);
    sd[tid] = d;
    __syncthreads();
    for (int o = 64; o > 0; o >>= 1) {
        if (tid < o) sd[tid] += sd[tid + o];
        __syncthreads();
    }
    if (tid == 0) out[r] = sm[0] + logf(ss[0]) - sd[0];
}

// ---------------- attention score (all-half in, half out) ------------------------
#define LDH 72
#define STG_LD 68
__global__ void __launch_bounds__(256)
k_attn_score(const __half* __restrict__ Q, const __half* __restrict__ Bm,
             const float* __restrict__ bias, __half* __restrict__ Out,
             int jStride, int bOffB, int mode) {
    int i0 = blockIdx.y * 64, j0 = blockIdx.x * 64;
    if (mode == 0) { if (j0 >= i0 + MLEN + 64) return; }
    else           { if (i0 + j0 < 384) return; }

    int g = blockIdx.z;
    int b = g >> 4, h = g & 15;
    const __half* Ab = Q + (size_t)b * HD + (size_t)h * DH;
    const __half* Bb = Bm + (size_t)b * bOffB + (size_t)h * DH;
    const float* bs = bias + (size_t)h * DH;

    __shared__ __align__(16) char sbuf[2 * 64 * LDH * 2];
    __half (*As)[LDH] = (__half(*)[LDH])sbuf;
    __half (*Bs)[LDH] = (__half(*)[LDH])(sbuf + 64 * LDH * 2);
    float* stage = (float*)sbuf;

    int tid = threadIdx.x;
    for (int t = tid; t < 1024; t += 256) {
        int row = t >> 4, c4 = (t & 15) << 2;
        const __half* qa = Ab + (size_t)(i0 + row) * (BSZ * HD) + c4;
#pragma unroll
        for (int u = 0; u < 4; u++)
            As[c4 + u][row] = __float2half_rn(__half2float(qa[u]) + bs[c4 + u]);
        const __half* kb = Bb + (size_t)(j0 + row) * jStride + c4;
#pragma unroll
        for (int u = 0; u < 4; u++)
            Bs[c4 + u][row] = kb[u];
    }
    __syncthreads();

    int warp = tid >> 5;
    int mr = warp & 3;
    int nc0 = (warp >> 2) * 2;
    HFragC c[2];
    wmma::fill_fragment(c[0], 0.0f);
    wmma::fill_fragment(c[1], 0.0f);
#pragma unroll
    for (int ks = 0; ks < 4; ks++) {
        HFragA a;
        wmma::load_matrix_sync(a, &As[ks * 16][mr * 16], LDH);
#pragma unroll
        for (int t = 0; t < 2; t++) {
            HFragB bf;
            wmma::load_matrix_sync(bf, &Bs[ks * 16][(nc0 + t) * 16], LDH);
            wmma::mma_sync(c[t], a, bf, c[t]);
        }
    }
    __syncthreads();
#pragma unroll
    for (int t = 0; t < 2; t++)
        wmma::store_matrix_sync(stage + (mr * 16) * STG_LD + (nc0 + t) * 16,
                                c[t], STG_LD, wmma::mem_row_major);
    __syncthreads();

    __half* O = Out + (size_t)g * QLEN * KLEN;
    for (int idx = tid; idx < 64 * 32; idx += 256) {
        int row = idx >> 5, c2 = (idx & 31) << 1;
        __half2 hv = __floats2half2_rn(stage[row * STG_LD + c2],
                                       stage[row * STG_LD + c2 + 1]);
        *(__half2*)(O + (size_t)(i0 + row) * KLEN + j0 + c2) = hv;
    }
}

// ---------------- rel-shift + mask + softmax (half) ------------------------------
__global__ void __launch_bounds__(256)
k_softmax(__half* __restrict__ AC, const __half* __restrict__ BD) {
    int g = blockIdx.y, i = blockIdx.x;
    __half* ac = AC + (size_t)g * QLEN * KLEN + (size_t)i * KLEN;
    const __half* bd = BD + (size_t)g * QLEN * KLEN + (size_t)i * KLEN;
    int tid = threadIdx.x;
    __shared__ float red[256];
    float s[4];
#pragma unroll
    for (int u = 0; u < 4; u++) {
        int j = tid + u * 256;
        bool valid = (j <= i + MLEN);
        s[u] = valid ? (__half2float(ac[j]) + __half2float(bd[j + (QLEN - 1) - i])) * ATT_SCALE
                     : NEGV;
    }
    float m = fmaxf(fmaxf(s[0], s[1]), fmaxf(s[2], s[3]));
    red[tid] = m;
    __syncthreads();
    for (int o = 128; o > 0; o >>= 1) {
        if (tid < o) red[tid] = fmaxf(red[tid], red[tid + o]);
        __syncthreads();
    }
    float M = red[0];
    __syncthreads();
    float e[4], sum = 0.f;
#pragma unroll
    for (int u = 0; u < 4; u++) {
        e[u] = (s[u] > 0.5f * NEGV) ? expf(s[u] - M) : 0.f;
        sum += e[u];
    }
    red[tid] = sum;
    __syncthreads();
    for (int o = 128; o > 0; o >>= 1) {
        if (tid < o) red[tid] += red[tid + o];
        __syncthreads();
    }
    float inv = 1.f / red[0];
#pragma unroll
    for (int u = 0; u < 4; u++) ac[tid + u * 256] = __float2half_rn(e[u] * inv);
}

// ---------------- P @ V (all-half, half out, masked skip) ------------------------
__global__ void __launch_bounds__(256)
k_attn_pv(const __half* __restrict__ P, const __half* __restrict__ KV,
          __half* __restrict__ vec) {
    int g = blockIdx.y;
    int b = g >> 4, h = g & 15;
    int i0 = blockIdx.x * 64;
    const int kt_end = min(KLEN, i0 + 64 + MLEN);
    const __half* Pb = P + (size_t)g * QLEN * KLEN;
    const __half* Vb = KV + (size_t)b * (2 * HD) + HD + (size_t)h * DH;
    __shared__ __half Ps[2][32][LDH];
    __shared__ __half Vs[2][32][LDH];
    __shared__ float pvstg[8][16][36];
    int tid = threadIdx.x;
    int warp = tid >> 5, lane = tid & 31;
    int mr = warp & 3;
    int nc0 = (warp >> 2) * 2;

    uint4 rp, rv;
    auto ldg = [&](int kt) {
        int prow = tid >> 2, pc8 = (tid & 3) << 3;
        rp = *(const uint4*)(Pb + (size_t)(i0 + prow) * KLEN + kt + pc8);
        int vrow = tid >> 3, vc8 = (tid & 7) << 3;
        rv = *(const uint4*)(Vb + (size_t)(kt + vrow) * (BSZ * 2 * HD) + vc8);
    };
    auto sts = [&](int s) {
        int prow = tid >> 2, pc8 = (tid & 3) << 3;
        const __half* hp = (const __half*)&rp;
#pragma unroll
        for (int j = 0; j < 8; j++) Ps[s][pc8 + j][prow] = hp[j];
        int vrow = tid >> 3, vc8 = (tid & 7) << 3;
        *(uint4*)&Vs[s][vrow][vc8] = rv;
    };

    HFragC c[2];
    wmma::fill_fragment(c[0], 0.0f);
    wmma::fill_fragment(c[1], 0.0f);

    ldg(0);
    sts(0);
    __syncthreads();
    int s = 0;
    for (int kt = 0; kt < kt_end; kt += 32) {
        bool nxt = (kt + 32) < kt_end;
        if (nxt) ldg(kt + 32);
#pragma unroll
        for (int ks = 0; ks < 2; ks++) {
            HFragA a;
            wmma::load_matrix_sync(a, &Ps[s][ks * 16][mr * 16], LDH);
#pragma unroll
            for (int t = 0; t < 2; t++) {
                HFragB bf;
                wmma::load_matrix_sync(bf, &Vs[s][ks * 16][(nc0 + t) * 16], LDH);
                wmma::mma_sync(c[t], a, bf, c[t]);
            }
        }
        if (nxt) {
            sts(s ^ 1);
            __syncthreads();
            s ^= 1;
        }
    }
#pragma unroll
    for (int t = 0; t < 2; t++)
        wmma::store_matrix_sync(&pvstg[warp][0][t * 16], c[t], 36, wmma::mem_row_major);
    __syncwarp();
    for (int idx = lane; idx < 16 * 16; idx += 32) {
        int row = idx >> 4, c2 = (idx & 15) << 1;
        __half2 hv = __floats2half2_rn(pvstg[warp][row][c2], pvstg[warp][row][c2 + 1]);
        *(__half2*)(vec + ((size_t)(i0 + mr * 16 + row) * BSZ + b) * HD
                        + (size_t)h * DH + nc0 * 16 + c2) = hv;
    }
}

// ---------------- layernorm(residual): fp32 out + fp16 out -----------------------
__global__ void __launch_bounds__(256)
k_ln(const float* __restrict__ X, const float* __restrict__ R,
     const float* __restrict__ gw, const float* __restrict__ bw,
     float* __restrict__ out, __half* __restrict__ outh) {
    int r = blockIdx.x;
    int tid = threadIdx.x;
    __shared__ float red[256];
    float x[4];
#pragma unroll
    for (int u = 0; u < 4; u++) {
        int d = tid + u * 256;
        x[u] = X[(size_t)r * DM + d] + R[(size_t)r * DM + d];
    }
    float s = x[0] + x[1] + x[2] + x[3];
    red[tid] = s;
    __syncthreads();
    for (int o = 128; o > 0; o >>= 1) {
        if (tid < o) red[tid] += red[tid + o];
        __syncthreads();
    }
    float mu = red[0] * (1.f / DM);
    __syncthreads();
    float v = 0.f;
#pragma unroll
    for (int u = 0; u < 4; u++) { float dd = x[u] - mu; v += dd * dd; }
    red[tid] = v;
    __syncthreads();
    for (int o = 128; o > 0; o >>= 1) {
        if (tid < o) red[tid] += red[tid + o];
        __syncthreads();
    }
    float rstd = rsqrtf(red[0] * (1.f / DM) + 1e-5f);
#pragma unroll
    for (int u = 0; u < 4; u++) {
        int d = tid + u * 256;
        float y = (x[u] - mu) * rstd * gw[d] + bw[d];
        out[(size_t)r * DM + d] = y;
        outh[(size_t)r * DM + d] = __float2half_rn(y);
    }
}

// ---------------- host orchestration ---------------------------------------------

static void* sym(const void* s) {
    void* p = nullptr;
    cudaGetSymbolAddress(&p, s);
    return p;
}

extern "C" void kernel_launch(void* const* d_in, const int* in_sizes, int n_in,
                              void* d_out, int out_size) {
    const int*   data   = (const int*)  d_in[0];
    const int*   target = (const int*)  d_in[1];
    const float* memory = (const float*)d_in[2];
    const float* embW   = (const float*)d_in[3];
    const float* rwb    = (const float*)d_in[4];
    const float* rrb    = (const float*)d_in[5];
    const float* Wq     = (const float*)d_in[6];
    const float* Wkv    = (const float*)d_in[7];
    const float* Wr     = (const float*)d_in[8];
    const float* Wo     = (const float*)d_in[9];
    const float* W1     = (const float*)d_in[10];
    const float* b1     = (const float*)d_in[11];
    const float* W2     = (const float*)d_in[12];
    const float* b2     = (const float*)d_in[13];
    const float* ln1g   = (const float*)d_in[14];
    const float* ln1b   = (const float*)d_in[15];
    const float* ln2g   = (const float*)d_in[16];
    const float* ln2b   = (const float*)d_in[17];

    float* out = (float*)d_out;
    float* loss_out = out;
    float* mems_out = out + (size_t)QLEN * BSZ;

    float*  big   = (float*)sym(g_big);
    __half* ac_h  = (__half*)big;
    __half* bd_h  = ac_h + SCORE_ELEMS;
    float*  core  = (float*)sym(g_core);
    float*  tmp   = (float*)sym(g_tmp);
    float*  pm    = tmp;                           // 4096 x NPART
    float*  ps    = tmp + (size_t)NROW * NPART;    // 4096 x NPART
    __half* coreh = (__half*)sym(h_core);
    __half* xmemh = (__half*)sym(h_xmem);
    __half* posh  = (__half*)sym(h_pos);
    __half* qh    = (__half*)sym(h_q);
    __half* kvh   = (__half*)sym(h_kv);
    __half* rkh   = (__half*)sym(h_rk);
    __half* vech  = (__half*)sym(h_vec);
    __half* ffh   = (__half*)sym(h_ff);
    __half* wqh   = (__half*)sym(h_wq);
    __half* wkvh  = (__half*)sym(h_wkv);
    __half* wrh   = (__half*)sym(h_wr);
    __half* woh   = (__half*)sym(h_wo);
    __half* w1h   = (__half*)sym(h_w1);
    __half* w2h   = (__half*)sym(h_w2);
    __half* embh  = (__half*)sym(h_emb);

    cudaFuncSetAttribute(k_wgemm<0,0>, cudaFuncAttributeMaxDynamicSharedMemorySize, WG_SMEM);
    cudaFuncSetAttribute(k_wgemm<0,1>, cudaFuncAttributeMaxDynamicSharedMemorySize, WG_SMEM);
    cudaFuncSetAttribute(k_logits, cudaFuncAttributeMaxDynamicSharedMemorySize, WG_SMEM);

    const size_t layerF = (size_t)QLEN * BSZ * DM;
    const int copy4 = (int)(layerF / 4);
    const int copy8 = (int)(layerF / 8);

    const size_t outN = (size_t)out_size;
    const size_t lossN = (size_t)QLEN * BSZ;

    auto cvt = [&](const float* s, __half* d, size_t n) {
        int n8 = (int)(n / 8);
        k_f2h<<<(n8 + 255) / 256, 256>>>(s, d, n8);
    };

    cvt(Wq,  wqh,  (size_t)NLAYER * DM * HD);
    cvt(Wkv, wkvh, (size_t)NLAYER * DM * 2 * HD);
    cvt(Wr,  wrh,  (size_t)NLAYER * DM * HD);
    cvt(Wo,  woh,  (size_t)NLAYER * HD * DM);
    cvt(W1,  w1h,  (size_t)NLAYER * DM * DI);
    cvt(W2,  w2h,  (size_t)NLAYER * DI * DM);
    cvt(embW, embh, (size_t)VOCAB * DM);

    k_embed<<<NROW, 256>>>(data, embW, core, coreh);
    k_pos<<<dim3(KLEN, 4), 256>>>(posh);
    if (lossN + layerF <= outN)
        k_copy4<<<copy4 / 256, 256>>>((const float4*)core, (float4*)mems_out, copy4);

    // all 6 layers' rk = pos @ Wr[l] in ONE batched launch (grid.z = 6)
    k_wgemm<0,1><<<dim3(HD / 256, KLEN / 128, NLAYER), 256, WG_SMEM>>>(
        posh, wrh, nullptr, rkh, KLEN, HD, DM, 0,
        (size_t)DM * HD, (size_t)KLEN * HD);

    for (int l = 0; l < NLAYER; l++) {
        cvt(memory + (size_t)l * layerF, xmemh, layerF);
        k_copyh<<<copy8 / 256, 256>>>((const uint4*)coreh, (uint4*)(xmemh + layerF), copy8);

        k_wgemm<0,1><<<dim3(HD / 256, NROW / 128), 256, WG_SMEM>>>(
            coreh, wqh + (size_t)l * DM * HD, nullptr, qh, NROW, HD, DM, 0, 0, 0);
        k_wgemm<0,1><<<dim3(2 * HD / 256, KROW / 128), 256, WG_SMEM>>>(
            xmemh, wkvh + (size_t)l * DM * 2 * HD, nullptr, kvh, KROW, 2 * HD, DM, 0, 0, 0);

        k_attn_score<<<dim3(KLEN / 64, QLEN / 64, BSZ * NH), 256>>>(
            qh, kvh, rwb, ac_h, BSZ * 2 * HD, 2 * HD, 0);
        k_attn_score<<<dim3(KLEN / 64, QLEN / 64, BSZ * NH), 256>>>(
            qh, rkh + (size_t)l * KLEN * HD, rrb, bd_h, HD, 0, 1);

        k_softmax<<<dim3(QLEN, BSZ * NH), 256>>>(ac_h, bd_h);
        k_attn_pv<<<dim3(QLEN / 64, BSZ * NH), 256>>>(ac_h, kvh, vech);

        k_wgemm<0,0><<<dim3(DM / 256, NROW / 128), 256, WG_SMEM>>>(
            vech, woh + (size_t)l * HD * DM, nullptr, tmp, NROW, DM, HD, 0, 0, 0);
        k_ln<<<NROW, 256>>>(core, tmp, ln1g + (size_t)l * DM, ln1b + (size_t)l * DM,
                            core, coreh);

        k_wgemm<0,1><<<dim3(DI / 256, NROW / 128), 256, WG_SMEM>>>(
            coreh, w1h + (size_t)l * DM * DI, b1 + (size_t)l * DI, ffh, NROW, DI, DM, 1, 0, 0);
        k_wgemm<0,0><<<dim3(DM / 256, NROW / 128), 256, WG_SMEM>>>(
            ffh, w2h + (size_t)l * DI * DM, b2 + (size_t)l * DM, tmp, NROW, DM, DI, 0, 0, 0);
        k_ln<<<NROW, 256>>>(core, tmp, ln2g + (size_t)l * DM, ln2b + (size_t)l * DM,
                            core, coreh);

        if (l < NLAYER - 1 && lossN + (size_t)(l + 2) * layerF <= outN)
            k_copy4<<<copy4 / 256, 256>>>((const float4*)core,
                                          (float4*)(mems_out + (size_t)(l + 1) * layerF), copy4);
    }

    k_logits<<<dim3(VOCAB / 256, NROW / 128), 256, WG_SMEM>>>(
        coreh, embh, pm, ps, VOCAB, DM);
    k_loss_final<<<NROW, 128>>>(pm, ps, coreh, embh, target, loss_out);
}